// round 2
// baseline (speedup 1.0000x reference)
#include <cuda_runtime.h>
#include <math.h>

#define BB   2
#define SS   2048
#define DIN  2048
#define NH   16
#define NKV  4
#define HD   128
#define GRP  4          // NH / NKV
#define SCALING 0.0625f // 256^-0.5
#define EPS  1e-6f

// ---------------- scratch (allocation-free: __device__ globals) ----------------
__device__ float g_q  [BB*SS*NH *HD];   // (b, s, h, d)
__device__ float g_k  [BB*SS*NKV*HD];   // (b, s, kv, d)
__device__ float g_v  [BB*SS*NKV*HD];   // (b, s, kv, d)
__device__ float g_ctx[BB*SS*NH *HD];   // (b, s, h, d)

// ---------------- SGEMM: C[M,N] = A[M,K] * B[K,N], 128x128 block, 8x8 micro ----
// Requires M%128==0, N%128==0, K%8==0 (true for all calls here).
__global__ __launch_bounds__(256)
void sgemm_kernel(const float* __restrict__ A, const float* __restrict__ Bm,
                  float* __restrict__ C, int M, int N, int K)
{
    __shared__ float As[8][128];   // transposed: As[k][m]
    __shared__ float Bs[8][128];   // Bs[k][n]

    const int tid = threadIdx.x;
    const int tx  = tid & 15;
    const int ty  = tid >> 4;
    const int n0  = blockIdx.x * 128;
    const int m0  = blockIdx.y * 128;

    const int am = tid >> 1;          // 0..127
    const int ak = (tid & 1) * 4;     // 0 or 4
    const int bk = tid >> 5;          // 0..7
    const int bn = (tid & 31) * 4;    // 0..124

    float acc[8][8];
    #pragma unroll
    for (int i = 0; i < 8; i++)
        #pragma unroll
        for (int j = 0; j < 8; j++) acc[i][j] = 0.f;

    for (int k0 = 0; k0 < K; k0 += 8) {
        float4 va = *(const float4*)&A[(size_t)(m0 + am) * K + k0 + ak];
        As[ak + 0][am] = va.x;
        As[ak + 1][am] = va.y;
        As[ak + 2][am] = va.z;
        As[ak + 3][am] = va.w;
        *(float4*)&Bs[bk][bn] = *(const float4*)&Bm[(size_t)(k0 + bk) * N + n0 + bn];
        __syncthreads();

        #pragma unroll
        for (int k = 0; k < 8; k++) {
            float4 a0 = *(float4*)&As[k][8 * ty];
            float4 a1 = *(float4*)&As[k][8 * ty + 4];
            float4 b0 = *(float4*)&Bs[k][8 * tx];
            float4 b1 = *(float4*)&Bs[k][8 * tx + 4];
            float a[8] = {a0.x, a0.y, a0.z, a0.w, a1.x, a1.y, a1.z, a1.w};
            float b[8] = {b0.x, b0.y, b0.z, b0.w, b1.x, b1.y, b1.z, b1.w};
            #pragma unroll
            for (int i = 0; i < 8; i++)
                #pragma unroll
                for (int j = 0; j < 8; j++)
                    acc[i][j] = fmaf(a[i], b[j], acc[i][j]);
        }
        __syncthreads();
    }

    #pragma unroll
    for (int i = 0; i < 8; i++) {
        size_t row = (size_t)(m0 + 8 * ty + i) * N + n0 + 8 * tx;
        float4 c0 = {acc[i][0], acc[i][1], acc[i][2], acc[i][3]};
        float4 c1 = {acc[i][4], acc[i][5], acc[i][6], acc[i][7]};
        *(float4*)&C[row]     = c0;
        *(float4*)&C[row + 4] = c1;
    }
}

// ---------------- RMSNorm + RoPE (+ optional q scaling), in place ----------------
// One block of 128 threads per (b, s, head) row. data layout: row-major over rows.
__global__ __launch_bounds__(128)
void norm_rope_kernel(float* __restrict__ data,
                      const float* __restrict__ cosb, const float* __restrict__ sinb,
                      const float* __restrict__ scale, int heads, float extra_scale)
{
    const int r = blockIdx.x;                 // (b*SS + s)*heads + h
    const int s = (r / heads) % SS;
    const int d = threadIdx.x;                // 0..127
    float* row = data + (size_t)r * HD;

    float val = row[d];
    float sq = val * val;
    #pragma unroll
    for (int off = 16; off; off >>= 1)
        sq += __shfl_xor_sync(0xffffffffu, sq, off);

    __shared__ float red[4];
    if ((d & 31) == 0) red[d >> 5] = sq;
    __syncthreads();
    float ss = red[0] + red[1] + red[2] + red[3];
    float rinv = rsqrtf(ss * (1.0f / HD) + EPS);
    float nrm = val * rinv * scale[d];

    __shared__ float buf[HD];
    buf[d] = nrm;
    __syncthreads();
    float partner = (d < HD / 2) ? -buf[d + HD / 2] : buf[d - HD / 2];
    float out = nrm * cosb[(size_t)s * HD + d] + partner * sinb[(size_t)s * HD + d];
    row[d] = out * extra_scale;
}

// ---------------- causal flash attention ----------------
// grid: (SS/64, NH, BB), 256 threads. 64 q-rows per block, k-tiles of 64.
// smem: Qts[128][64] | Kts[128][64] | Vs[64][128] | Ps[64][64]  = 114688 B
#define ATT_SMEM_FLOATS (128*64 + 128*64 + 64*128 + 64*64)

__global__ __launch_bounds__(256)
void attn_kernel(const float* __restrict__ q, const float* __restrict__ k,
                 const float* __restrict__ v, float* __restrict__ ctx)
{
    extern __shared__ float smem[];
    float* Qts = smem;                       // [d][i], 128x64
    float* Kts = smem + 128 * 64;            // [d][j], 128x64
    float* Vs  = smem + 2 * 128 * 64;        // [j][d], 64x128
    float* Ps  = smem + 3 * 128 * 64;        // [i][j], 64x64

    const int qb = blockIdx.x, h = blockIdx.y, b = blockIdx.z;
    const int kv = h / GRP;
    const int q0 = qb * 64;
    const int tid = threadIdx.x;
    const int tx = tid & 15, ty = tid >> 4;

    // load Q tile transposed
    for (int idx = tid; idx < 64 * (HD / 4); idx += 256) {
        int i  = idx >> 5;           // 0..63
        int dq = (idx & 31) * 4;     // 0..124
        float4 vq = *(const float4*)&q[((((size_t)b * SS + q0 + i) * NH) + h) * HD + dq];
        Qts[(dq + 0) * 64 + i] = vq.x;
        Qts[(dq + 1) * 64 + i] = vq.y;
        Qts[(dq + 2) * 64 + i] = vq.z;
        Qts[(dq + 3) * 64 + i] = vq.w;
    }

    float o[4][8];
    float m_r[4], l_r[4];
    #pragma unroll
    for (int i = 0; i < 4; i++) {
        m_r[i] = -1e30f; l_r[i] = 0.f;
        #pragma unroll
        for (int d = 0; d < 8; d++) o[i][d] = 0.f;
    }

    for (int kb = 0; kb <= qb; kb++) {
        const int k0 = kb * 64;
        __syncthreads();   // previous iter's Ps/Vs reads done; Q store visible (iter 0)

        for (int idx = tid; idx < 64 * (HD / 4); idx += 256) {
            int j  = idx >> 5;
            int dq = (idx & 31) * 4;
            size_t base = (((size_t)b * SS + k0 + j) * NKV + kv) * HD + dq;
            float4 vk = *(const float4*)&k[base];
            Kts[(dq + 0) * 64 + j] = vk.x;
            Kts[(dq + 1) * 64 + j] = vk.y;
            Kts[(dq + 2) * 64 + j] = vk.z;
            Kts[(dq + 3) * 64 + j] = vk.w;
            *(float4*)&Vs[j * HD + dq] = *(const float4*)&v[base];
        }
        __syncthreads();

        // S = Q K^T (4x4 per thread)
        float sc[4][4];
        #pragma unroll
        for (int i = 0; i < 4; i++)
            #pragma unroll
            for (int j = 0; j < 4; j++) sc[i][j] = 0.f;

        #pragma unroll 4
        for (int d = 0; d < HD; d++) {
            float4 aq = *(float4*)&Qts[d * 64 + 4 * ty];
            float4 ak = *(float4*)&Kts[d * 64 + 4 * tx];
            float qa[4] = {aq.x, aq.y, aq.z, aq.w};
            float ka[4] = {ak.x, ak.y, ak.z, ak.w};
            #pragma unroll
            for (int i = 0; i < 4; i++)
                #pragma unroll
                for (int j = 0; j < 4; j++)
                    sc[i][j] = fmaf(qa[i], ka[j], sc[i][j]);
        }

        if (kb == qb) {   // causal mask on diagonal tile
            #pragma unroll
            for (int i = 0; i < 4; i++)
                #pragma unroll
                for (int j = 0; j < 4; j++)
                    if (k0 + 4 * tx + j > q0 + 4 * ty + i) sc[i][j] = -1e30f;
        }

        // online softmax
        float mt[4];
        #pragma unroll
        for (int i = 0; i < 4; i++) {
            mt[i] = fmaxf(fmaxf(sc[i][0], sc[i][1]), fmaxf(sc[i][2], sc[i][3]));
            #pragma unroll
            for (int off = 1; off < 16; off <<= 1)
                mt[i] = fmaxf(mt[i], __shfl_xor_sync(0xffffffffu, mt[i], off));
        }
        float p[4][4], ls[4], alpha[4];
        #pragma unroll
        for (int i = 0; i < 4; i++) {
            float mn = fmaxf(m_r[i], mt[i]);
            alpha[i] = __expf(m_r[i] - mn);
            m_r[i] = mn;
            ls[i] = 0.f;
            #pragma unroll
            for (int j = 0; j < 4; j++) {
                p[i][j] = __expf(sc[i][j] - mn);
                ls[i] += p[i][j];
            }
            #pragma unroll
            for (int off = 1; off < 16; off <<= 1)
                ls[i] += __shfl_xor_sync(0xffffffffu, ls[i], off);
            l_r[i] = l_r[i] * alpha[i] + ls[i];
            #pragma unroll
            for (int d = 0; d < 8; d++) o[i][d] *= alpha[i];
        }

        #pragma unroll
        for (int i = 0; i < 4; i++)
            #pragma unroll
            for (int j = 0; j < 4; j++)
                Ps[(4 * ty + i) * 64 + 4 * tx + j] = p[i][j];
        __syncthreads();

        // O += P V (4 rows x 8 cols per thread)
        #pragma unroll 2
        for (int j = 0; j < 64; j++) {
            float4 v0 = *(float4*)&Vs[j * HD + 8 * tx];
            float4 v1 = *(float4*)&Vs[j * HD + 8 * tx + 4];
            float vb[8] = {v0.x, v0.y, v0.z, v0.w, v1.x, v1.y, v1.z, v1.w};
            #pragma unroll
            for (int i = 0; i < 4; i++) {
                float pv = Ps[(4 * ty + i) * 64 + j];
                #pragma unroll
                for (int d = 0; d < 8; d++)
                    o[i][d] = fmaf(pv, vb[d], o[i][d]);
            }
        }
    }

    // epilogue: divide by l, write ctx in (b, s, h, d)
    #pragma unroll
    for (int i = 0; i < 4; i++) {
        float inv = 1.0f / l_r[i];
        size_t base = (((size_t)b * SS + q0 + 4 * ty + i) * NH + h) * HD + 8 * tx;
        float4 c0 = {o[i][0] * inv, o[i][1] * inv, o[i][2] * inv, o[i][3] * inv};
        float4 c1 = {o[i][4] * inv, o[i][5] * inv, o[i][6] * inv, o[i][7] * inv};
        *(float4*)&ctx[base]     = c0;
        *(float4*)&ctx[base + 4] = c1;
    }
}

// ---------------- launch ----------------
extern "C" void kernel_launch(void* const* d_in, const int* in_sizes, int n_in,
                              void* d_out, int out_size)
{
    const float* x       = (const float*)d_in[0];
    // d_in[1] = mask (bool) — causal structure is known, unused
    const float* cosb    = (const float*)d_in[2];
    const float* sinb    = (const float*)d_in[3];
    const float* Wq      = (const float*)d_in[4];
    const float* Wk      = (const float*)d_in[5];
    const float* Wv      = (const float*)d_in[6];
    const float* Wo      = (const float*)d_in[7];
    const float* q_scale = (const float*)d_in[8];
    const float* k_scale = (const float*)d_in[9];
    float* out = (float*)d_out;

    float *q, *k, *v, *ctx;
    cudaGetSymbolAddress((void**)&q,   g_q);
    cudaGetSymbolAddress((void**)&k,   g_k);
    cudaGetSymbolAddress((void**)&v,   g_v);
    cudaGetSymbolAddress((void**)&ctx, g_ctx);

    const int M = BB * SS;   // 4096

    // projections
    sgemm_kernel<<<dim3(NH  * HD / 128, M / 128), 256>>>(x, Wq, q, M, NH  * HD, DIN);
    sgemm_kernel<<<dim3(NKV * HD / 128, M / 128), 256>>>(x, Wk, k, M, NKV * HD, DIN);
    sgemm_kernel<<<dim3(NKV * HD / 128, M / 128), 256>>>(x, Wv, v, M, NKV * HD, DIN);

    // rmsnorm + rope (+ q scaling)
    norm_rope_kernel<<<BB * SS * NH,  128>>>(q, cosb, sinb, q_scale, NH,  SCALING);
    norm_rope_kernel<<<BB * SS * NKV, 128>>>(k, cosb, sinb, k_scale, NKV, 1.0f);

    // attention
    cudaFuncSetAttribute(attn_kernel, cudaFuncAttributeMaxDynamicSharedMemorySize,
                         ATT_SMEM_FLOATS * (int)sizeof(float));
    attn_kernel<<<dim3(SS / 64, NH, BB), 256, ATT_SMEM_FLOATS * sizeof(float)>>>(q, k, v, ctx);

    // output projection
    sgemm_kernel<<<dim3(DIN / 128, M / 128), 256>>>(ctx, Wo, out, M, DIN, DIN);
}

// round 3
// speedup vs baseline: 3.0668x; 3.0668x over previous
#include <cuda_runtime.h>
#include <math.h>
#include <stdint.h>

#define BB   2
#define SS   2048
#define DIN  2048
#define NH   16
#define NKV  4
#define HD   128
#define GRP  4          // NH / NKV
#define SCALING 0.0625f // 256^-0.5
#define EPS  1e-6f

// ---------------- scratch (allocation-free: __device__ globals) ----------------
__device__ float g_q  [BB*SS*NH *HD];   // (b, s, h, d)
__device__ float g_k  [BB*SS*NKV*HD];   // (b, s, kv, d)
__device__ float g_v  [BB*SS*NKV*HD];   // (b, s, kv, d)
__device__ float g_ctx[BB*SS*NH *HD];   // (b, s, h, d)

// fp32 -> tf32 bit pattern, round-to-nearest (unbiased; truncation bias would
// accumulate to ~1e-3 over K=2048 dot products).
__device__ __forceinline__ uint32_t f2tf(float f) {
    uint32_t u;
    asm("cvt.rna.tf32.f32 %0, %1;" : "=r"(u) : "f"(f));
    return u;
}

#define MMA_TF32(C0,C1,C2,C3,A0,A1,A2,A3,B0,B1)                                \
    asm volatile("mma.sync.aligned.m16n8k8.row.col.f32.tf32.tf32.f32 "         \
                 "{%0,%1,%2,%3},{%4,%5,%6,%7},{%8,%9},{%0,%1,%2,%3};"          \
                 : "+f"(C0), "+f"(C1), "+f"(C2), "+f"(C3)                      \
                 : "r"(A0), "r"(A1), "r"(A2), "r"(A3), "r"(B0), "r"(B1))

// ---------------- tf32 GEMM: C[M,N] = A[M,K] * B[K,N] ----------------
// 128x128 CTA tile, k-tile 16, 8 warps of 64x32, double-buffered smem.
// As[m][k] stride 20, Bs[k][n] stride 136: both conflict-free for the
// m16n8k8 fragment LDS patterns (verified bank math).
#define ASTR 20
#define BSTR 136

__global__ __launch_bounds__(256)
void gemm_tf32(const float* __restrict__ A, const float* __restrict__ B,
               float* __restrict__ C, int M, int N, int K)
{
    __shared__ uint32_t As[2][128 * ASTR];
    __shared__ uint32_t Bs[2][16 * BSTR];

    const int tid  = threadIdx.x;
    const int lane = tid & 31;
    const int warp = tid >> 5;
    const int wm   = (warp >> 2) * 64;   // 0 or 64
    const int wn   = (warp & 3) * 32;    // 0,32,64,96
    const int m0   = blockIdx.y * 128;
    const int n0   = blockIdx.x * 128;

    // gmem staging assignment
    const int ar = tid >> 1;            // 0..127
    const int ac = (tid & 1) * 8;       // 0 or 8
    const int br = tid >> 4;            // 0..15
    const int bc = (tid & 15) * 8;      // 0..120
    const float* Ap = A + (size_t)(m0 + ar) * K + ac;
    const float* Bp = B + (size_t)br * N + n0 + bc;

    float c[4][4][4];
    #pragma unroll
    for (int mt = 0; mt < 4; mt++)
        #pragma unroll
        for (int nt = 0; nt < 4; nt++)
            #pragma unroll
            for (int e = 0; e < 4; e++) c[mt][nt][e] = 0.f;

    const int KT = K >> 4;

    // preload tile 0
    {
        float4 a0 = *(const float4*)(Ap);
        float4 a1 = *(const float4*)(Ap + 4);
        float4 b0 = *(const float4*)(Bp);
        float4 b1 = *(const float4*)(Bp + 4);
        uint32_t* pa = &As[0][ar * ASTR + ac];
        pa[0]=f2tf(a0.x); pa[1]=f2tf(a0.y); pa[2]=f2tf(a0.z); pa[3]=f2tf(a0.w);
        pa[4]=f2tf(a1.x); pa[5]=f2tf(a1.y); pa[6]=f2tf(a1.z); pa[7]=f2tf(a1.w);
        uint32_t* pb = &Bs[0][br * BSTR + bc];
        pb[0]=f2tf(b0.x); pb[1]=f2tf(b0.y); pb[2]=f2tf(b0.z); pb[3]=f2tf(b0.w);
        pb[4]=f2tf(b1.x); pb[5]=f2tf(b1.y); pb[6]=f2tf(b1.z); pb[7]=f2tf(b1.w);
    }
    __syncthreads();

    int buf = 0;
    for (int kt = 0; kt < KT; kt++) {
        float4 na0, na1, nb0, nb1;
        const bool has_next = (kt + 1 < KT);
        if (has_next) {
            const float* ap = Ap + (size_t)(kt + 1) * 16;
            const float* bp = Bp + (size_t)(kt + 1) * 16 * N;
            na0 = *(const float4*)(ap);
            na1 = *(const float4*)(ap + 4);
            nb0 = *(const float4*)(bp);
            nb1 = *(const float4*)(bp + 4);
        }

        #pragma unroll
        for (int ks = 0; ks < 2; ks++) {
            uint32_t af[4][4], bf[4][2];
            #pragma unroll
            for (int mt = 0; mt < 4; mt++) {
                const uint32_t* p = &As[buf][(wm + mt * 16 + (lane >> 2)) * ASTR
                                            + ks * 8 + (lane & 3)];
                af[mt][0] = p[0];
                af[mt][1] = p[8 * ASTR];
                af[mt][2] = p[4];
                af[mt][3] = p[8 * ASTR + 4];
            }
            #pragma unroll
            for (int nt = 0; nt < 4; nt++) {
                const uint32_t* p = &Bs[buf][(ks * 8 + (lane & 3)) * BSTR
                                             + wn + nt * 8 + (lane >> 2)];
                bf[nt][0] = p[0];
                bf[nt][1] = p[4 * BSTR];
            }
            #pragma unroll
            for (int mt = 0; mt < 4; mt++)
                #pragma unroll
                for (int nt = 0; nt < 4; nt++)
                    MMA_TF32(c[mt][nt][0], c[mt][nt][1], c[mt][nt][2], c[mt][nt][3],
                             af[mt][0], af[mt][1], af[mt][2], af[mt][3],
                             bf[nt][0], bf[nt][1]);
        }

        if (has_next) {
            uint32_t* pa = &As[buf ^ 1][ar * ASTR + ac];
            pa[0]=f2tf(na0.x); pa[1]=f2tf(na0.y); pa[2]=f2tf(na0.z); pa[3]=f2tf(na0.w);
            pa[4]=f2tf(na1.x); pa[5]=f2tf(na1.y); pa[6]=f2tf(na1.z); pa[7]=f2tf(na1.w);
            uint32_t* pb = &Bs[buf ^ 1][br * BSTR + bc];
            pb[0]=f2tf(nb0.x); pb[1]=f2tf(nb0.y); pb[2]=f2tf(nb0.z); pb[3]=f2tf(nb0.w);
            pb[4]=f2tf(nb1.x); pb[5]=f2tf(nb1.y); pb[6]=f2tf(nb1.z); pb[7]=f2tf(nb1.w);
            __syncthreads();
            buf ^= 1;
        }
    }

    // epilogue
    #pragma unroll
    for (int mt = 0; mt < 4; mt++) {
        #pragma unroll
        for (int nt = 0; nt < 4; nt++) {
            int r  = m0 + wm + mt * 16 + (lane >> 2);
            int cc = n0 + wn + nt * 8 + 2 * (lane & 3);
            *(float2*)&C[(size_t)r * N + cc]       = make_float2(c[mt][nt][0], c[mt][nt][1]);
            *(float2*)&C[(size_t)(r + 8) * N + cc] = make_float2(c[mt][nt][2], c[mt][nt][3]);
        }
    }
}

// ---------------- RMSNorm + RoPE (+ optional q scaling), in place ----------------
__global__ __launch_bounds__(128)
void norm_rope_kernel(float* __restrict__ data,
                      const float* __restrict__ cosb, const float* __restrict__ sinb,
                      const float* __restrict__ scale, int heads, float extra_scale)
{
    const int r = blockIdx.x;                 // (b*SS + s)*heads + h
    const int s = (r / heads) % SS;
    const int d = threadIdx.x;                // 0..127
    float* row = data + (size_t)r * HD;

    float val = row[d];
    float sq = val * val;
    #pragma unroll
    for (int off = 16; off; off >>= 1)
        sq += __shfl_xor_sync(0xffffffffu, sq, off);

    __shared__ float red[4];
    if ((d & 31) == 0) red[d >> 5] = sq;
    __syncthreads();
    float ss = red[0] + red[1] + red[2] + red[3];
    float rinv = rsqrtf(ss * (1.0f / HD) + EPS);
    float nrm = val * rinv * scale[d];

    __shared__ float buf[HD];
    buf[d] = nrm;
    __syncthreads();
    float partner = (d < HD / 2) ? -buf[d + HD / 2] : buf[d - HD / 2];
    float out = nrm * cosb[(size_t)s * HD + d] + partner * sinb[(size_t)s * HD + d];
    row[d] = out * extra_scale;
}

// ---------------- causal flash attention, tf32 mma ----------------
// 128 q-rows per CTA, 64-key tiles. 8 warps, warp w owns q-rows [16w, 16w+16).
// smem (uint32 units, padded strides, all fragment loads conflict-free):
//   Qs[128][132] | Ks[64][132] | Vs[64][136] | Ps[128][68]  = 171008 B
#define QS_STR 132
#define KS_STR 132
#define VS_STR 136
#define PS_STR 68
#define QS_OFF 0
#define KS_OFF (128 * QS_STR)                 // 16896
#define VS_OFF (KS_OFF + 64 * KS_STR)         // 25344
#define PS_OFF (VS_OFF + 64 * VS_STR)         // 34048
#define ATT_SMEM_U32 (PS_OFF + 128 * PS_STR)  // 42752
#define ATT_SMEM_BYTES (ATT_SMEM_U32 * 4)     // 171008

__global__ __launch_bounds__(256)
void attn_tf32(const float* __restrict__ q, const float* __restrict__ k,
               const float* __restrict__ v, float* __restrict__ ctx)
{
    extern __shared__ uint32_t sm[];
    uint32_t* Qs = sm + QS_OFF;
    uint32_t* Ks = sm + KS_OFF;
    uint32_t* Vs = sm + VS_OFF;
    uint32_t* Ps = sm + PS_OFF;

    const int qb = blockIdx.x, h = blockIdx.y, b = blockIdx.z;
    const int kvh = h / GRP;
    const int q0 = qb * 128;
    const int tid = threadIdx.x;
    const int lane = tid & 31;
    const int warp = tid >> 5;       // 0..7
    const int wm = warp * 16;        // warp's q-row offset in tile
    const int lq = lane >> 2;        // 0..7 (row within m-tile)
    const int lr = lane & 3;         // 0..3

    // load Q tile (128 x 128), tf32-converted
    for (int idx = tid; idx < 128 * 32; idx += 256) {
        int i  = idx >> 5;
        int dq = (idx & 31) * 4;
        float4 vq = *(const float4*)&q[((((size_t)b * SS + q0 + i) * NH) + h) * HD + dq];
        uint32_t* p = &Qs[i * QS_STR + dq];
        p[0] = f2tf(vq.x); p[1] = f2tf(vq.y); p[2] = f2tf(vq.z); p[3] = f2tf(vq.w);
    }

    float o[16][4];
    #pragma unroll
    for (int nt = 0; nt < 16; nt++)
        #pragma unroll
        for (int e = 0; e < 4; e++) o[nt][e] = 0.f;
    float mrow[2] = {-1e30f, -1e30f};
    float lrow[2] = {0.f, 0.f};

    const int kbmax = qb * 2 + 1;
    for (int kb = 0; kb <= kbmax; kb++) {
        const int k0 = kb * 64;
        __syncthreads();  // prev iter done reading Ks/Vs

        for (int idx = tid; idx < 64 * 32; idx += 256) {
            int j  = idx >> 5;
            int dq = (idx & 31) * 4;
            size_t base = (((size_t)b * SS + k0 + j) * NKV + kvh) * HD + dq;
            float4 vk = *(const float4*)&k[base];
            float4 vv = *(const float4*)&v[base];
            uint32_t* pk = &Ks[j * KS_STR + dq];
            pk[0] = f2tf(vk.x); pk[1] = f2tf(vk.y); pk[2] = f2tf(vk.z); pk[3] = f2tf(vk.w);
            uint32_t* pv = &Vs[j * VS_STR + dq];
            pv[0] = f2tf(vv.x); pv[1] = f2tf(vv.y); pv[2] = f2tf(vv.z); pv[3] = f2tf(vv.w);
        }
        __syncthreads();

        // warp-level early out: entire warp tile masked?
        const bool active = (k0 <= q0 + wm + 15);
        if (active) {
            // ---- S = Q K^T : warp computes 16 x 64 ----
            float s[8][4];
            #pragma unroll
            for (int nt = 0; nt < 8; nt++)
                #pragma unroll
                for (int e = 0; e < 4; e++) s[nt][e] = 0.f;

            #pragma unroll 4
            for (int ks = 0; ks < 16; ks++) {
                uint32_t af[4];
                const uint32_t* pq = &Qs[(wm + lq) * QS_STR + ks * 8 + lr];
                af[0] = pq[0];
                af[1] = pq[8 * QS_STR];
                af[2] = pq[4];
                af[3] = pq[8 * QS_STR + 4];
                #pragma unroll
                for (int nt = 0; nt < 8; nt++) {
                    const uint32_t* pk = &Ks[(nt * 8 + lq) * KS_STR + ks * 8 + lr];
                    uint32_t b0 = pk[0];
                    uint32_t b1 = pk[4];
                    MMA_TF32(s[nt][0], s[nt][1], s[nt][2], s[nt][3],
                             af[0], af[1], af[2], af[3], b0, b1);
                }
            }

            // causal mask on diagonal tiles
            if (kb >= qb * 2) {
                int i0 = q0 + wm + lq;
                #pragma unroll
                for (int nt = 0; nt < 8; nt++) {
                    int j0 = k0 + nt * 8 + 2 * lr;
                    if (j0     > i0)     s[nt][0] = -1e30f;
                    if (j0 + 1 > i0)     s[nt][1] = -1e30f;
                    if (j0     > i0 + 8) s[nt][2] = -1e30f;
                    if (j0 + 1 > i0 + 8) s[nt][3] = -1e30f;
                }
            }

            // ---- online softmax (rows lq and lq+8 within warp tile) ----
            #pragma unroll
            for (int hh = 0; hh < 2; hh++) {
                float rmax = -1e30f;
                #pragma unroll
                for (int nt = 0; nt < 8; nt++)
                    rmax = fmaxf(rmax, fmaxf(s[nt][2 * hh], s[nt][2 * hh + 1]));
                rmax = fmaxf(rmax, __shfl_xor_sync(0xffffffffu, rmax, 1));
                rmax = fmaxf(rmax, __shfl_xor_sync(0xffffffffu, rmax, 2));

                float mnew  = fmaxf(mrow[hh], rmax);
                float alpha = __expf(mrow[hh] - mnew);
                mrow[hh] = mnew;

                float rsum = 0.f;
                int prow = (wm + lq + 8 * hh) * PS_STR + 2 * lr;
                #pragma unroll
                for (int nt = 0; nt < 8; nt++) {
                    float p0 = __expf(s[nt][2 * hh]     - mnew);
                    float p1 = __expf(s[nt][2 * hh + 1] - mnew);
                    rsum += p0 + p1;
                    uint2 pp = make_uint2(f2tf(p0), f2tf(p1));
                    *(uint2*)&Ps[prow + nt * 8] = pp;
                }
                rsum += __shfl_xor_sync(0xffffffffu, rsum, 1);
                rsum += __shfl_xor_sync(0xffffffffu, rsum, 2);
                lrow[hh] = lrow[hh] * alpha + rsum;

                #pragma unroll
                for (int nt = 0; nt < 16; nt++) {
                    o[nt][2 * hh]     *= alpha;
                    o[nt][2 * hh + 1] *= alpha;
                }
            }
            __syncwarp();  // Ps is warp-private (rows wm..wm+15) but cross-lane

            // ---- O += P V : warp computes 16 x 128 ----
            #pragma unroll 2
            for (int ks = 0; ks < 8; ks++) {
                uint32_t af[4];
                const uint32_t* pp = &Ps[(wm + lq) * PS_STR + ks * 8 + lr];
                af[0] = pp[0];
                af[1] = pp[8 * PS_STR];
                af[2] = pp[4];
                af[3] = pp[8 * PS_STR + 4];
                #pragma unroll
                for (int nt = 0; nt < 16; nt++) {
                    const uint32_t* pv = &Vs[(ks * 8 + lr) * VS_STR + nt * 8 + lq];
                    uint32_t b0 = pv[0];
                    uint32_t b1 = pv[4 * VS_STR];
                    MMA_TF32(o[nt][0], o[nt][1], o[nt][2], o[nt][3],
                             af[0], af[1], af[2], af[3], b0, b1);
                }
            }
        }
    }

    // epilogue
    #pragma unroll
    for (int hh = 0; hh < 2; hh++) {
        float inv = 1.0f / lrow[hh];
        int row = q0 + wm + lq + 8 * hh;
        size_t base = (((size_t)b * SS + row) * NH + h) * HD;
        #pragma unroll
        for (int nt = 0; nt < 16; nt++) {
            int d = nt * 8 + 2 * lr;
            *(float2*)&ctx[base + d] =
                make_float2(o[nt][2 * hh] * inv, o[nt][2 * hh + 1] * inv);
        }
    }
}

// ---------------- launch ----------------
extern "C" void kernel_launch(void* const* d_in, const int* in_sizes, int n_in,
                              void* d_out, int out_size)
{
    const float* x       = (const float*)d_in[0];
    // d_in[1] = mask (bool) — causal structure known, unused
    const float* cosb    = (const float*)d_in[2];
    const float* sinb    = (const float*)d_in[3];
    const float* Wq      = (const float*)d_in[4];
    const float* Wk      = (const float*)d_in[5];
    const float* Wv      = (const float*)d_in[6];
    const float* Wo      = (const float*)d_in[7];
    const float* q_scale = (const float*)d_in[8];
    const float* k_scale = (const float*)d_in[9];
    float* out = (float*)d_out;

    float *q, *k, *v, *ctx;
    cudaGetSymbolAddress((void**)&q,   g_q);
    cudaGetSymbolAddress((void**)&k,   g_k);
    cudaGetSymbolAddress((void**)&v,   g_v);
    cudaGetSymbolAddress((void**)&ctx, g_ctx);

    const int M = BB * SS;   // 4096

    // projections (tf32 tensor cores)
    gemm_tf32<<<dim3(NH  * HD / 128, M / 128), 256>>>(x, Wq, q, M, NH  * HD, DIN);
    gemm_tf32<<<dim3(NKV * HD / 128, M / 128), 256>>>(x, Wk, k, M, NKV * HD, DIN);
    gemm_tf32<<<dim3(NKV * HD / 128, M / 128), 256>>>(x, Wv, v, M, NKV * HD, DIN);

    // rmsnorm + rope (+ q scaling)
    norm_rope_kernel<<<BB * SS * NH,  128>>>(q, cosb, sinb, q_scale, NH,  SCALING);
    norm_rope_kernel<<<BB * SS * NKV, 128>>>(k, cosb, sinb, k_scale, NKV, 1.0f);

    // attention (tf32 tensor cores)
    cudaFuncSetAttribute(attn_tf32, cudaFuncAttributeMaxDynamicSharedMemorySize,
                         ATT_SMEM_BYTES);
    attn_tf32<<<dim3(SS / 128, NH, BB), 256, ATT_SMEM_BYTES>>>(q, k, v, ctx);

    // output projection
    gemm_tf32<<<dim3(DIN / 128, M / 128), 256>>>(ctx, Wo, out, M, DIN, DIN);
}

// round 10
// speedup vs baseline: 4.1997x; 1.3694x over previous
#include <cuda_runtime.h>
#include <cuda_fp16.h>
#include <math.h>
#include <stdint.h>

#define BB   2
#define SS   2048
#define DIN  2048
#define NH   16
#define NKV  4
#define HD   128
#define GRP  4          // NH / NKV
#define SCALING 0.0625f // 256^-0.5
#define EPS  1e-6f

// ---------------- scratch (allocation-free: __device__ globals) ----------------
__device__ float g_q  [BB*SS*NH *HD];   // fp32, R2 layout (b, s, h, d)
__device__ float g_k  [BB*SS*NKV*HD];
__device__ float g_v  [BB*SS*NKV*HD];
__device__ float g_ctx[BB*SS*NH *HD];
__device__ __half g_xh [BB*SS*DIN];     // x fp16 [M][K]
__device__ __half g_ch [BB*SS*NH*HD];   // ctx fp16 [M][K]
__device__ __half g_wqT[DIN*NH*HD];     // [N][K] fp16 transposed weights
__device__ __half g_wkT[DIN*NKV*HD];
__device__ __half g_wvT[DIN*NKV*HD];
__device__ __half g_woT[DIN*NH*HD];

// ================= mma =================
__device__ __forceinline__ uint32_t f2tf(float f) {
    uint32_t u;
    asm("cvt.rna.tf32.f32 %0, %1;" : "=r"(u) : "f"(f));
    return u;
}
#define MMA_F16(C0,C1,C2,C3, A0,A1,A2,A3, B0,B1)                               \
    asm volatile("mma.sync.aligned.m16n8k16.row.col.f32.f16.f16.f32 "          \
                 "{%0,%1,%2,%3},{%4,%5,%6,%7},{%8,%9},{%0,%1,%2,%3};"          \
                 : "+f"(C0), "+f"(C1), "+f"(C2), "+f"(C3)                      \
                 : "r"(A0), "r"(A1), "r"(A2), "r"(A3), "r"(B0), "r"(B1))
#define MMA_TF32(C0,C1,C2,C3,A0,A1,A2,A3,B0,B1)                                \
    asm volatile("mma.sync.aligned.m16n8k8.row.col.f32.tf32.tf32.f32 "         \
                 "{%0,%1,%2,%3},{%4,%5,%6,%7},{%8,%9},{%0,%1,%2,%3};"          \
                 : "+f"(C0), "+f"(C1), "+f"(C2), "+f"(C3)                      \
                 : "r"(A0), "r"(A1), "r"(A2), "r"(A3), "r"(B0), "r"(B1))

// ================= preprocessing =================
__global__ __launch_bounds__(256)
void transpose_f16(const float* __restrict__ W, __half* __restrict__ T, int K, int N)
{
    __shared__ float t[32][33];
    const int tx = threadIdx.x & 31, ty = threadIdx.x >> 5;
    const int kb = blockIdx.y * 32, nb = blockIdx.x * 32;
    #pragma unroll
    for (int i = 0; i < 4; i++)
        t[ty + i * 8][tx] = W[(size_t)(kb + ty + i * 8) * N + nb + tx];
    __syncthreads();
    #pragma unroll
    for (int i = 0; i < 4; i++)
        T[(size_t)(nb + ty + i * 8) * K + kb + tx] = __float2half(t[tx][ty + i * 8]);
}

__global__ __launch_bounds__(256)
void convert_f16(const float* __restrict__ X, __half* __restrict__ H, int n)
{
    int i = (blockIdx.x * 256 + threadIdx.x) * 8;
    if (i < n) {
        float4 a = *(const float4*)&X[i];
        float4 b = *(const float4*)&X[i + 4];
        __half2 h0 = __floats2half2_rn(a.x, a.y);
        __half2 h1 = __floats2half2_rn(a.z, a.w);
        __half2 h2 = __floats2half2_rn(b.x, b.y);
        __half2 h3 = __floats2half2_rn(b.z, b.w);
        *(uint4*)&H[i] = make_uint4(*(uint32_t*)&h0, *(uint32_t*)&h1,
                                    *(uint32_t*)&h2, *(uint32_t*)&h3);
    }
}

// ================= fp16 GEMM: C[M,N] = A[M,K] * B[N,K]^T, fp32 out =========
// 128x128 CTA tile, k-tile 64 halves (32 words), 8 warps x (64x32).
// smem word stride 36 -> fragment banks 4*lq+lr, conflict-free.
#define GW 36
#define GTILE (128 * GW)
#define GEMM_SMEM_BYTES (4 * GTILE * 4)    // 73728 B

__global__ __launch_bounds__(256)
void gemm_f16s(const __half* __restrict__ A, const __half* __restrict__ B,
               float* __restrict__ C, int M, int N, int K)
{
    extern __shared__ uint32_t sg[];
    const int tid  = threadIdx.x;
    const int lane = tid & 31;
    const int warp = tid >> 5;
    const int wm   = (warp >> 2) * 64;
    const int wn   = (warp & 3) * 32;
    const int m0   = blockIdx.y * 128;
    const int n0   = blockIdx.x * 128;
    const int lq   = lane >> 2, lr = lane & 3;

    const int srow = tid >> 1;
    const int sh   = (tid & 1) * 32;
    const __half* Ap = A + (size_t)(m0 + srow) * K + sh;
    const __half* Bp = B + (size_t)(n0 + srow) * K + sh;
    const uint32_t wst = srow * GW + (tid & 1) * 16;

    float c[4][4][4];
    #pragma unroll
    for (int mt = 0; mt < 4; mt++)
        #pragma unroll
        for (int nt = 0; nt < 4; nt++)
            #pragma unroll
            for (int e = 0; e < 4; e++) c[mt][nt][e] = 0.f;

    const int KT = K >> 6;

    #pragma unroll
    for (int i = 0; i < 4; i++) {
        *(uint4*)&sg[0 * GTILE + wst + i * 4] = *(const uint4*)(Ap + i * 8);
        *(uint4*)&sg[1 * GTILE + wst + i * 4] = *(const uint4*)(Bp + i * 8);
    }
    __syncthreads();

    int buf = 0;
    for (int kt = 0; kt < KT; kt++) {
        uint4 ra[4], rb[4];
        const bool has_next = (kt + 1 < KT);
        if (has_next) {
            const __half* ap = Ap + (size_t)(kt + 1) * 64;
            const __half* bp = Bp + (size_t)(kt + 1) * 64;
            #pragma unroll
            for (int i = 0; i < 4; i++) {
                ra[i] = *(const uint4*)(ap + i * 8);
                rb[i] = *(const uint4*)(bp + i * 8);
            }
        }

        const uint32_t* As = sg + buf * 2 * GTILE;
        const uint32_t* Bs = As + GTILE;
        #pragma unroll
        for (int ks = 0; ks < 4; ks++) {
            const int kw0 = ks * 8;
            uint32_t af[4][4], bf[4][2];
            #pragma unroll
            for (int mt = 0; mt < 4; mt++) {
                const uint32_t* p = &As[(wm + mt * 16 + lq) * GW + kw0 + lr];
                af[mt][0] = p[0];
                af[mt][1] = p[8 * GW];
                af[mt][2] = p[4];
                af[mt][3] = p[8 * GW + 4];
            }
            #pragma unroll
            for (int nt = 0; nt < 4; nt++) {
                const uint32_t* p = &Bs[(wn + nt * 8 + lq) * GW + kw0 + lr];
                bf[nt][0] = p[0];
                bf[nt][1] = p[4];
            }
            #pragma unroll
            for (int mt = 0; mt < 4; mt++)
                #pragma unroll
                for (int nt = 0; nt < 4; nt++)
                    MMA_F16(c[mt][nt][0], c[mt][nt][1], c[mt][nt][2], c[mt][nt][3],
                            af[mt][0], af[mt][1], af[mt][2], af[mt][3],
                            bf[nt][0], bf[nt][1]);
        }

        if (has_next) {
            uint32_t* dst = sg + (buf ^ 1) * 2 * GTILE;
            #pragma unroll
            for (int i = 0; i < 4; i++) {
                *(uint4*)&dst[wst + i * 4]         = ra[i];
                *(uint4*)&dst[GTILE + wst + i * 4] = rb[i];
            }
            __syncthreads();
            buf ^= 1;
        }
    }

    #pragma unroll
    for (int mt = 0; mt < 4; mt++) {
        #pragma unroll
        for (int nt = 0; nt < 4; nt++) {
            int r  = m0 + wm + mt * 16 + lq;
            int cc = n0 + wn + nt * 8 + 2 * lr;
            *(float2*)&C[(size_t)r * N + cc]       = make_float2(c[mt][nt][0], c[mt][nt][1]);
            *(float2*)&C[(size_t)(r + 8) * N + cc] = make_float2(c[mt][nt][2], c[mt][nt][3]);
        }
    }
}

// ---------------- RMSNorm + RoPE, fp32 in place (R2 verbatim) ----------------
__global__ __launch_bounds__(128)
void norm_rope_kernel(float* __restrict__ data,
                      const float* __restrict__ cosb, const float* __restrict__ sinb,
                      const float* __restrict__ scale, int heads, float extra_scale)
{
    const int r = blockIdx.x;
    const int s = (r / heads) % SS;
    const int d = threadIdx.x;
    float* row = data + (size_t)r * HD;

    float val = row[d];
    float sq = val * val;
    #pragma unroll
    for (int off = 16; off; off >>= 1)
        sq += __shfl_xor_sync(0xffffffffu, sq, off);

    __shared__ float red[4];
    if ((d & 31) == 0) red[d >> 5] = sq;
    __syncthreads();
    float ss = red[0] + red[1] + red[2] + red[3];
    float rinv = rsqrtf(ss * (1.0f / HD) + EPS);
    float nrm = val * rinv * scale[d];

    __shared__ float buf[HD];
    buf[d] = nrm;
    __syncthreads();
    float partner = (d < HD / 2) ? -buf[d + HD / 2] : buf[d - HD / 2];
    float out = nrm * cosb[(size_t)s * HD + d] + partner * sinb[(size_t)s * HD + d];
    row[d] = out * extra_scale;
}

// ---------------- causal flash attention, tf32 mma (R2 verbatim) ----------------
#define QS_STR 132
#define KS_STR 132
#define VS_STR 136
#define PS_STR 68
#define QS_OFF 0
#define KS_OFF (128 * QS_STR)
#define VS_OFF (KS_OFF + 64 * KS_STR)
#define PS_OFF (VS_OFF + 64 * VS_STR)
#define ATT_SMEM_U32 (PS_OFF + 128 * PS_STR)
#define ATT_SMEM_BYTES (ATT_SMEM_U32 * 4)

__global__ __launch_bounds__(256)
void attn_tf32(const float* __restrict__ q, const float* __restrict__ k,
               const float* __restrict__ v, float* __restrict__ ctx)
{
    extern __shared__ uint32_t sm[];
    uint32_t* Qs = sm + QS_OFF;
    uint32_t* Ks = sm + KS_OFF;
    uint32_t* Vs = sm + VS_OFF;
    uint32_t* Ps = sm + PS_OFF;

    const int qb = blockIdx.x, h = blockIdx.y, b = blockIdx.z;
    const int kvh = h / GRP;
    const int q0 = qb * 128;
    const int tid = threadIdx.x;
    const int lane = tid & 31;
    const int warp = tid >> 5;
    const int wm = warp * 16;
    const int lq = lane >> 2;
    const int lr = lane & 3;

    for (int idx = tid; idx < 128 * 32; idx += 256) {
        int i  = idx >> 5;
        int dq = (idx & 31) * 4;
        float4 vq = *(const float4*)&q[((((size_t)b * SS + q0 + i) * NH) + h) * HD + dq];
        uint32_t* p = &Qs[i * QS_STR + dq];
        p[0] = f2tf(vq.x); p[1] = f2tf(vq.y); p[2] = f2tf(vq.z); p[3] = f2tf(vq.w);
    }

    float o[16][4];
    #pragma unroll
    for (int nt = 0; nt < 16; nt++)
        #pragma unroll
        for (int e = 0; e < 4; e++) o[nt][e] = 0.f;
    float mrow[2] = {-1e30f, -1e30f};
    float lrow[2] = {0.f, 0.f};

    const int kbmax = qb * 2 + 1;
    for (int kb = 0; kb <= kbmax; kb++) {
        const int k0 = kb * 64;
        __syncthreads();

        for (int idx = tid; idx < 64 * 32; idx += 256) {
            int j  = idx >> 5;
            int dq = (idx & 31) * 4;
            size_t base = (((size_t)b * SS + k0 + j) * NKV + kvh) * HD + dq;
            float4 vk = *(const float4*)&k[base];
            float4 vv = *(const float4*)&v[base];
            uint32_t* pk = &Ks[j * KS_STR + dq];
            pk[0] = f2tf(vk.x); pk[1] = f2tf(vk.y); pk[2] = f2tf(vk.z); pk[3] = f2tf(vk.w);
            uint32_t* pv = &Vs[j * VS_STR + dq];
            pv[0] = f2tf(vv.x); pv[1] = f2tf(vv.y); pv[2] = f2tf(vv.z); pv[3] = f2tf(vv.w);
        }
        __syncthreads();

        const bool active = (k0 <= q0 + wm + 15);
        if (active) {
            float s[8][4];
            #pragma unroll
            for (int nt = 0; nt < 8; nt++)
                #pragma unroll
                for (int e = 0; e < 4; e++) s[nt][e] = 0.f;

            #pragma unroll 4
            for (int ks = 0; ks < 16; ks++) {
                uint32_t af[4];
                const uint32_t* pq = &Qs[(wm + lq) * QS_STR + ks * 8 + lr];
                af[0] = pq[0];
                af[1] = pq[8 * QS_STR];
                af[2] = pq[4];
                af[3] = pq[8 * QS_STR + 4];
                #pragma unroll
                for (int nt = 0; nt < 8; nt++) {
                    const uint32_t* pk = &Ks[(nt * 8 + lq) * KS_STR + ks * 8 + lr];
                    MMA_TF32(s[nt][0], s[nt][1], s[nt][2], s[nt][3],
                             af[0], af[1], af[2], af[3], pk[0], pk[4]);
                }
            }

            if (kb >= qb * 2) {
                int i0 = q0 + wm + lq;
                #pragma unroll
                for (int nt = 0; nt < 8; nt++) {
                    int j0 = k0 + nt * 8 + 2 * lr;
                    if (j0     > i0)     s[nt][0] = -1e30f;
                    if (j0 + 1 > i0)     s[nt][1] = -1e30f;
                    if (j0     > i0 + 8) s[nt][2] = -1e30f;
                    if (j0 + 1 > i0 + 8) s[nt][3] = -1e30f;
                }
            }

            #pragma unroll
            for (int hh = 0; hh < 2; hh++) {
                float rmax = -1e30f;
                #pragma unroll
                for (int nt = 0; nt < 8; nt++)
                    rmax = fmaxf(rmax, fmaxf(s[nt][2 * hh], s[nt][2 * hh + 1]));
                rmax = fmaxf(rmax, __shfl_xor_sync(0xffffffffu, rmax, 1));
                rmax = fmaxf(rmax, __shfl_xor_sync(0xffffffffu, rmax, 2));

                float mnew  = fmaxf(mrow[hh], rmax);
                float alpha = __expf(mrow[hh] - mnew);
                mrow[hh] = mnew;

                float rsum = 0.f;
                int prow = (wm + lq + 8 * hh) * PS_STR + 2 * lr;
                #pragma unroll
                for (int nt = 0; nt < 8; nt++) {
                    float p0 = __expf(s[nt][2 * hh]     - mnew);
                    float p1 = __expf(s[nt][2 * hh + 1] - mnew);
                    rsum += p0 + p1;
                    uint2 pp = make_uint2(f2tf(p0), f2tf(p1));
                    *(uint2*)&Ps[prow + nt * 8] = pp;
                }
                rsum += __shfl_xor_sync(0xffffffffu, rsum, 1);
                rsum += __shfl_xor_sync(0xffffffffu, rsum, 2);
                lrow[hh] = lrow[hh] * alpha + rsum;

                #pragma unroll
                for (int nt = 0; nt < 16; nt++) {
                    o[nt][2 * hh]     *= alpha;
                    o[nt][2 * hh + 1] *= alpha;
                }
            }
            __syncwarp();

            #pragma unroll 2
            for (int ks = 0; ks < 8; ks++) {
                uint32_t af[4];
                const uint32_t* pp = &Ps[(wm + lq) * PS_STR + ks * 8 + lr];
                af[0] = pp[0];
                af[1] = pp[8 * PS_STR];
                af[2] = pp[4];
                af[3] = pp[8 * PS_STR + 4];
                #pragma unroll
                for (int nt = 0; nt < 16; nt++) {
                    const uint32_t* pv = &Vs[(ks * 8 + lr) * VS_STR + nt * 8 + lq];
                    MMA_TF32(o[nt][0], o[nt][1], o[nt][2], o[nt][3],
                             af[0], af[1], af[2], af[3], pv[0], pv[4 * VS_STR]);
                }
            }
        }
    }

    #pragma unroll
    for (int hh = 0; hh < 2; hh++) {
        float inv = 1.0f / lrow[hh];
        int row = q0 + wm + lq + 8 * hh;
        size_t base = (((size_t)b * SS + row) * NH + h) * HD;
        #pragma unroll
        for (int nt = 0; nt < 16; nt++) {
            int d = nt * 8 + 2 * lr;
            *(float2*)&ctx[base + d] =
                make_float2(o[nt][2 * hh] * inv, o[nt][2 * hh + 1] * inv);
        }
    }
}

// ---------------- launch ----------------
extern "C" void kernel_launch(void* const* d_in, const int* in_sizes, int n_in,
                              void* d_out, int out_size)
{
    const float* x       = (const float*)d_in[0];
    const float* cosb    = (const float*)d_in[2];
    const float* sinb    = (const float*)d_in[3];
    const float* Wq      = (const float*)d_in[4];
    const float* Wk      = (const float*)d_in[5];
    const float* Wv      = (const float*)d_in[6];
    const float* Wo      = (const float*)d_in[7];
    const float* q_scale = (const float*)d_in[8];
    const float* k_scale = (const float*)d_in[9];
    float* out = (float*)d_out;

    float *q, *k, *v, *ctx;
    cudaGetSymbolAddress((void**)&q,   g_q);
    cudaGetSymbolAddress((void**)&k,   g_k);
    cudaGetSymbolAddress((void**)&v,   g_v);
    cudaGetSymbolAddress((void**)&ctx, g_ctx);
    __half *xh, *ch, *wqT, *wkT, *wvT, *woT;
    cudaGetSymbolAddress((void**)&xh,  g_xh);
    cudaGetSymbolAddress((void**)&ch,  g_ch);
    cudaGetSymbolAddress((void**)&wqT, g_wqT);
    cudaGetSymbolAddress((void**)&wkT, g_wkT);
    cudaGetSymbolAddress((void**)&wvT, g_wvT);
    cudaGetSymbolAddress((void**)&woT, g_woT);

    const int M = BB * SS;   // 4096

    // preprocessing: transpose weights to [N][K] fp16, convert x to fp16
    transpose_f16<<<dim3((NH * HD) / 32, DIN / 32), 256>>>(Wq, wqT, DIN, NH * HD);
    transpose_f16<<<dim3((NKV * HD) / 32, DIN / 32), 256>>>(Wk, wkT, DIN, NKV * HD);
    transpose_f16<<<dim3((NKV * HD) / 32, DIN / 32), 256>>>(Wv, wvT, DIN, NKV * HD);
    transpose_f16<<<dim3(DIN / 32, (NH * HD) / 32), 256>>>(Wo, woT, NH * HD, DIN);
    convert_f16<<<M * DIN / 8 / 256, 256>>>(x, xh, M * DIN);

    // projections (fp16 mma, fp32 out)
    cudaFuncSetAttribute(gemm_f16s, cudaFuncAttributeMaxDynamicSharedMemorySize,
                         GEMM_SMEM_BYTES);
    gemm_f16s<<<dim3((NH * HD) / 128, M / 128), 256, GEMM_SMEM_BYTES>>>(
        xh, wqT, q, M, NH * HD, DIN);
    gemm_f16s<<<dim3((NKV * HD) / 128, M / 128), 256, GEMM_SMEM_BYTES>>>(
        xh, wkT, k, M, NKV * HD, DIN);
    gemm_f16s<<<dim3((NKV * HD) / 128, M / 128), 256, GEMM_SMEM_BYTES>>>(
        xh, wvT, v, M, NKV * HD, DIN);

    // rmsnorm + rope (fp32, R2 verbatim)
    norm_rope_kernel<<<BB * SS * NH,  128>>>(q, cosb, sinb, q_scale, NH,  SCALING);
    norm_rope_kernel<<<BB * SS * NKV, 128>>>(k, cosb, sinb, k_scale, NKV, 1.0f);

    // attention (tf32, R2 verbatim)
    cudaFuncSetAttribute(attn_tf32, cudaFuncAttributeMaxDynamicSharedMemorySize,
                         ATT_SMEM_BYTES);
    attn_tf32<<<dim3(SS / 128, NH, BB), 256, ATT_SMEM_BYTES>>>(q, k, v, ctx);

    // output projection: ctx -> fp16, fp16 mma, fp32 out
    convert_f16<<<M * NH * HD / 8 / 256, 256>>>(ctx, ch, M * NH * HD);
    gemm_f16s<<<dim3(DIN / 128, M / 128), 256, GEMM_SMEM_BYTES>>>(
        ch, woT, out, M, DIN, DIN);
}

// round 12
// speedup vs baseline: 4.5636x; 1.0867x over previous
#include <cuda_runtime.h>
#include <cuda_fp16.h>
#include <math.h>
#include <stdint.h>

#define BB   2
#define SS   2048
#define DIN  2048
#define NH   16
#define NKV  4
#define HD   128
#define GRP  4          // NH / NKV
#define SCALING 0.0625f // 256^-0.5
#define EPS  1e-6f

// ---------------- scratch (allocation-free: __device__ globals) ----------------
__device__ float g_q  [BB*SS*NH *HD];   // fp32 (b, s, h, d)
__device__ float g_k  [BB*SS*NKV*HD];
__device__ float g_v  [BB*SS*NKV*HD];
__device__ __half g_xh [BB*SS*DIN];     // x fp16 [M][K]
__device__ __half g_ch [BB*SS*NH*HD];   // ctx fp16 [M][K] (written by attention)
__device__ __half g_wqT[DIN*NH*HD];     // [N][K] fp16 transposed weights
__device__ __half g_wkT[DIN*NKV*HD];
__device__ __half g_wvT[DIN*NKV*HD];
__device__ __half g_woT[DIN*NH*HD];

// ================= mma =================
__device__ __forceinline__ uint32_t f2tf(float f) {
    uint32_t u;
    asm("cvt.rna.tf32.f32 %0, %1;" : "=r"(u) : "f"(f));
    return u;
}
#define MMA_F16(C0,C1,C2,C3, A0,A1,A2,A3, B0,B1)                               \
    asm volatile("mma.sync.aligned.m16n8k16.row.col.f32.f16.f16.f32 "          \
                 "{%0,%1,%2,%3},{%4,%5,%6,%7},{%8,%9},{%0,%1,%2,%3};"          \
                 : "+f"(C0), "+f"(C1), "+f"(C2), "+f"(C3)                      \
                 : "r"(A0), "r"(A1), "r"(A2), "r"(A3), "r"(B0), "r"(B1))
#define MMA_TF32(C0,C1,C2,C3,A0,A1,A2,A3,B0,B1)                                \
    asm volatile("mma.sync.aligned.m16n8k8.row.col.f32.tf32.tf32.f32 "         \
                 "{%0,%1,%2,%3},{%4,%5,%6,%7},{%8,%9},{%0,%1,%2,%3};"          \
                 : "+f"(C0), "+f"(C1), "+f"(C2), "+f"(C3)                      \
                 : "r"(A0), "r"(A1), "r"(A2), "r"(A3), "r"(B0), "r"(B1))

// ================= preprocessing =================
__global__ __launch_bounds__(256)
void transpose_f16(const float* __restrict__ W, __half* __restrict__ T, int K, int N)
{
    __shared__ float t[32][33];
    const int tx = threadIdx.x & 31, ty = threadIdx.x >> 5;
    const int kb = blockIdx.y * 32, nb = blockIdx.x * 32;
    #pragma unroll
    for (int i = 0; i < 4; i++)
        t[ty + i * 8][tx] = W[(size_t)(kb + ty + i * 8) * N + nb + tx];
    __syncthreads();
    #pragma unroll
    for (int i = 0; i < 4; i++)
        T[(size_t)(nb + ty + i * 8) * K + kb + tx] = __float2half(t[tx][ty + i * 8]);
}

__global__ __launch_bounds__(256)
void convert_f16(const float* __restrict__ X, __half* __restrict__ H, int n)
{
    int i = (blockIdx.x * 256 + threadIdx.x) * 8;
    if (i < n) {
        float4 a = *(const float4*)&X[i];
        float4 b = *(const float4*)&X[i + 4];
        __half2 h0 = __floats2half2_rn(a.x, a.y);
        __half2 h1 = __floats2half2_rn(a.z, a.w);
        __half2 h2 = __floats2half2_rn(b.x, b.y);
        __half2 h3 = __floats2half2_rn(b.z, b.w);
        *(uint4*)&H[i] = make_uint4(*(uint32_t*)&h0, *(uint32_t*)&h1,
                                    *(uint32_t*)&h2, *(uint32_t*)&h3);
    }
}

// ================= fp16 GEMM (R10 verbatim, proven) =================
#define GW 36
#define GTILE (128 * GW)
#define GEMM_SMEM_BYTES (4 * GTILE * 4)    // 73728 B

__global__ __launch_bounds__(256)
void gemm_f16s(const __half* __restrict__ A, const __half* __restrict__ B,
               float* __restrict__ C, int M, int N, int K)
{
    extern __shared__ uint32_t sg[];
    const int tid  = threadIdx.x;
    const int lane = tid & 31;
    const int warp = tid >> 5;
    const int wm   = (warp >> 2) * 64;
    const int wn   = (warp & 3) * 32;
    const int m0   = blockIdx.y * 128;
    const int n0   = blockIdx.x * 128;
    const int lq   = lane >> 2, lr = lane & 3;

    const int srow = tid >> 1;
    const int sh   = (tid & 1) * 32;
    const __half* Ap = A + (size_t)(m0 + srow) * K + sh;
    const __half* Bp = B + (size_t)(n0 + srow) * K + sh;
    const uint32_t wst = srow * GW + (tid & 1) * 16;

    float c[4][4][4];
    #pragma unroll
    for (int mt = 0; mt < 4; mt++)
        #pragma unroll
        for (int nt = 0; nt < 4; nt++)
            #pragma unroll
            for (int e = 0; e < 4; e++) c[mt][nt][e] = 0.f;

    const int KT = K >> 6;

    #pragma unroll
    for (int i = 0; i < 4; i++) {
        *(uint4*)&sg[0 * GTILE + wst + i * 4] = *(const uint4*)(Ap + i * 8);
        *(uint4*)&sg[1 * GTILE + wst + i * 4] = *(const uint4*)(Bp + i * 8);
    }
    __syncthreads();

    int buf = 0;
    for (int kt = 0; kt < KT; kt++) {
        uint4 ra[4], rb[4];
        const bool has_next = (kt + 1 < KT);
        if (has_next) {
            const __half* ap = Ap + (size_t)(kt + 1) * 64;
            const __half* bp = Bp + (size_t)(kt + 1) * 64;
            #pragma unroll
            for (int i = 0; i < 4; i++) {
                ra[i] = *(const uint4*)(ap + i * 8);
                rb[i] = *(const uint4*)(bp + i * 8);
            }
        }

        const uint32_t* As = sg + buf * 2 * GTILE;
        const uint32_t* Bs = As + GTILE;
        #pragma unroll
        for (int ks = 0; ks < 4; ks++) {
            const int kw0 = ks * 8;
            uint32_t af[4][4], bf[4][2];
            #pragma unroll
            for (int mt = 0; mt < 4; mt++) {
                const uint32_t* p = &As[(wm + mt * 16 + lq) * GW + kw0 + lr];
                af[mt][0] = p[0];
                af[mt][1] = p[8 * GW];
                af[mt][2] = p[4];
                af[mt][3] = p[8 * GW + 4];
            }
            #pragma unroll
            for (int nt = 0; nt < 4; nt++) {
                const uint32_t* p = &Bs[(wn + nt * 8 + lq) * GW + kw0 + lr];
                bf[nt][0] = p[0];
                bf[nt][1] = p[4];
            }
            #pragma unroll
            for (int mt = 0; mt < 4; mt++)
                #pragma unroll
                for (int nt = 0; nt < 4; nt++)
                    MMA_F16(c[mt][nt][0], c[mt][nt][1], c[mt][nt][2], c[mt][nt][3],
                            af[mt][0], af[mt][1], af[mt][2], af[mt][3],
                            bf[nt][0], bf[nt][1]);
        }

        if (has_next) {
            uint32_t* dst = sg + (buf ^ 1) * 2 * GTILE;
            #pragma unroll
            for (int i = 0; i < 4; i++) {
                *(uint4*)&dst[wst + i * 4]         = ra[i];
                *(uint4*)&dst[GTILE + wst + i * 4] = rb[i];
            }
            __syncthreads();
            buf ^= 1;
        }
    }

    #pragma unroll
    for (int mt = 0; mt < 4; mt++) {
        #pragma unroll
        for (int nt = 0; nt < 4; nt++) {
            int r  = m0 + wm + mt * 16 + lq;
            int cc = n0 + wn + nt * 8 + 2 * lr;
            *(float2*)&C[(size_t)r * N + cc]       = make_float2(c[mt][nt][0], c[mt][nt][1]);
            *(float2*)&C[(size_t)(r + 8) * N + cc] = make_float2(c[mt][nt][2], c[mt][nt][3]);
        }
    }
}

// ---------------- RMSNorm + RoPE, fp32 in place (proven) ----------------
__global__ __launch_bounds__(128)
void norm_rope_kernel(float* __restrict__ data,
                      const float* __restrict__ cosb, const float* __restrict__ sinb,
                      const float* __restrict__ scale, int heads, float extra_scale)
{
    const int r = blockIdx.x;
    const int s = (r / heads) % SS;
    const int d = threadIdx.x;
    float* row = data + (size_t)r * HD;

    float val = row[d];
    float sq = val * val;
    #pragma unroll
    for (int off = 16; off; off >>= 1)
        sq += __shfl_xor_sync(0xffffffffu, sq, off);

    __shared__ float red[4];
    if ((d & 31) == 0) red[d >> 5] = sq;
    __syncthreads();
    float ss = red[0] + red[1] + red[2] + red[3];
    float rinv = rsqrtf(ss * (1.0f / HD) + EPS);
    float nrm = val * rinv * scale[d];

    __shared__ float buf[HD];
    buf[d] = nrm;
    __syncthreads();
    float partner = (d < HD / 2) ? -buf[d + HD / 2] : buf[d - HD / 2];
    float out = nrm * cosb[(size_t)s * HD + d] + partner * sinb[(size_t)s * HD + d];
    row[d] = out * extra_scale;
}

// ================= causal flash attention =================
// 64 q-rows/CTA, 128 threads (4 warps x 16 q-rows), 64-key tiles.
// Q/K staged fp16 (QH_STR = 68 words: HD=128 halves = 64 words + 4 pad —
// the R11 bug was using the GEMM k-tile stride 36 here).
// S = QK^T fp16 mma; P*V verbatim tf32. smem 87040 B -> 2 CTAs/SM.
#define QH_STR 68
#define VS_STR 136
#define PS_STR 68
#define QS_OFF 0
#define KS_OFF (64 * QH_STR)            // 4352
#define VS_OFF (KS_OFF + 64 * QH_STR)   // 8704
#define PS_OFF (VS_OFF + 64 * VS_STR)   // 17408
#define ATT_SMEM_U32 (PS_OFF + 64 * PS_STR)    // 21760
#define ATT_SMEM_BYTES (ATT_SMEM_U32 * 4)      // 87040

__global__ __launch_bounds__(128)
void attn_hyb(const float* __restrict__ q, const float* __restrict__ k,
              const float* __restrict__ v, __half* __restrict__ ctx)
{
    extern __shared__ uint32_t sm[];
    uint32_t* Qs = sm + QS_OFF;
    uint32_t* Ks = sm + KS_OFF;
    uint32_t* Vs = sm + VS_OFF;
    uint32_t* Ps = sm + PS_OFF;

    const int qb = blockIdx.x, h = blockIdx.y, b = blockIdx.z;
    const int kvh = h / GRP;
    const int q0 = qb * 64;
    const int tid = threadIdx.x;
    const int lane = tid & 31;
    const int warp = tid >> 5;       // 0..3
    const int wm = warp * 16;
    const int lq = lane >> 2;
    const int lr = lane & 3;

    // Q tile: 64 rows x 32 tasks; task = 4 floats -> 2 fp16 words.
    // Row coverage: 32 tasks x 2 words = 64 words = 128 halves ✓
    for (int idx = tid; idx < 64 * 32; idx += 128) {
        int i  = idx >> 5;
        int c4 = idx & 31;
        float4 vq = *(const float4*)&q[((((size_t)b * SS + q0 + i) * NH) + h) * HD + c4 * 4];
        __half2 h0 = __floats2half2_rn(vq.x, vq.y);
        __half2 h1 = __floats2half2_rn(vq.z, vq.w);
        *(uint2*)&Qs[i * QH_STR + c4 * 2] = make_uint2(*(uint32_t*)&h0, *(uint32_t*)&h1);
    }

    float o[16][4];
    #pragma unroll
    for (int nt = 0; nt < 16; nt++)
        #pragma unroll
        for (int e = 0; e < 4; e++) o[nt][e] = 0.f;
    float mrow[2] = {-1e30f, -1e30f};
    float lrow[2] = {0.f, 0.f};

    for (int kb = 0; kb <= qb; kb++) {
        const int k0 = kb * 64;
        __syncthreads();   // prev iter done reading; Q stores visible (iter 0)

        // K (fp16, 64 words/row) + V (tf32, 128 words/row)
        for (int idx = tid; idx < 64 * 32; idx += 128) {
            int j  = idx >> 5;
            int c4 = idx & 31;
            size_t base = (((size_t)b * SS + k0 + j) * NKV + kvh) * HD + c4 * 4;
            float4 vk = *(const float4*)&k[base];
            float4 vv = *(const float4*)&v[base];
            __half2 h0 = __floats2half2_rn(vk.x, vk.y);
            __half2 h1 = __floats2half2_rn(vk.z, vk.w);
            *(uint2*)&Ks[j * QH_STR + c4 * 2] = make_uint2(*(uint32_t*)&h0, *(uint32_t*)&h1);
            uint32_t* pv = &Vs[j * VS_STR + c4 * 4];
            pv[0] = f2tf(vv.x); pv[1] = f2tf(vv.y); pv[2] = f2tf(vv.z); pv[3] = f2tf(vv.w);
        }
        __syncthreads();

        const bool active = (k0 <= q0 + wm + 15);
        if (active) {
            // ---- S = Q K^T (fp16, 8 k16-steps over HD=128 halves) ----
            float s[8][4];
            #pragma unroll
            for (int nt = 0; nt < 8; nt++)
                #pragma unroll
                for (int e = 0; e < 4; e++) s[nt][e] = 0.f;

            #pragma unroll
            for (int ks = 0; ks < 8; ks++) {
                const int kw0 = ks * 8;
                uint32_t af[4];
                const uint32_t* pq = &Qs[(wm + lq) * QH_STR + kw0 + lr];
                af[0] = pq[0];
                af[1] = pq[8 * QH_STR];
                af[2] = pq[4];
                af[3] = pq[8 * QH_STR + 4];
                #pragma unroll
                for (int nt = 0; nt < 8; nt++) {
                    const uint32_t* pk = &Ks[(nt * 8 + lq) * QH_STR + kw0 + lr];
                    MMA_F16(s[nt][0], s[nt][1], s[nt][2], s[nt][3],
                            af[0], af[1], af[2], af[3], pk[0], pk[4]);
                }
            }

            // causal mask on the diagonal tile
            if (kb == qb) {
                int i0 = q0 + wm + lq;
                #pragma unroll
                for (int nt = 0; nt < 8; nt++) {
                    int j0 = k0 + nt * 8 + 2 * lr;
                    if (j0     > i0)     s[nt][0] = -1e30f;
                    if (j0 + 1 > i0)     s[nt][1] = -1e30f;
                    if (j0     > i0 + 8) s[nt][2] = -1e30f;
                    if (j0 + 1 > i0 + 8) s[nt][3] = -1e30f;
                }
            }

            // ---- online softmax (proven) ----
            #pragma unroll
            for (int hh = 0; hh < 2; hh++) {
                float rmax = -1e30f;
                #pragma unroll
                for (int nt = 0; nt < 8; nt++)
                    rmax = fmaxf(rmax, fmaxf(s[nt][2 * hh], s[nt][2 * hh + 1]));
                rmax = fmaxf(rmax, __shfl_xor_sync(0xffffffffu, rmax, 1));
                rmax = fmaxf(rmax, __shfl_xor_sync(0xffffffffu, rmax, 2));

                float mnew  = fmaxf(mrow[hh], rmax);
                float alpha = __expf(mrow[hh] - mnew);
                mrow[hh] = mnew;

                float rsum = 0.f;
                int prow = (wm + lq + 8 * hh) * PS_STR + 2 * lr;
                #pragma unroll
                for (int nt = 0; nt < 8; nt++) {
                    float p0 = __expf(s[nt][2 * hh]     - mnew);
                    float p1 = __expf(s[nt][2 * hh + 1] - mnew);
                    rsum += p0 + p1;
                    uint2 pp = make_uint2(f2tf(p0), f2tf(p1));
                    *(uint2*)&Ps[prow + nt * 8] = pp;
                }
                rsum += __shfl_xor_sync(0xffffffffu, rsum, 1);
                rsum += __shfl_xor_sync(0xffffffffu, rsum, 2);
                lrow[hh] = lrow[hh] * alpha + rsum;

                #pragma unroll
                for (int nt = 0; nt < 16; nt++) {
                    o[nt][2 * hh]     *= alpha;
                    o[nt][2 * hh + 1] *= alpha;
                }
            }
            __syncwarp();

            // ---- O += P V (tf32, proven) ----
            #pragma unroll 2
            for (int ks = 0; ks < 8; ks++) {
                uint32_t af[4];
                const uint32_t* pp = &Ps[(wm + lq) * PS_STR + ks * 8 + lr];
                af[0] = pp[0];
                af[1] = pp[8 * PS_STR];
                af[2] = pp[4];
                af[3] = pp[8 * PS_STR + 4];
                #pragma unroll
                for (int nt = 0; nt < 16; nt++) {
                    const uint32_t* pv = &Vs[(ks * 8 + lr) * VS_STR + nt * 8 + lq];
                    MMA_TF32(o[nt][0], o[nt][1], o[nt][2], o[nt][3],
                             af[0], af[1], af[2], af[3], pv[0], pv[4 * VS_STR]);
                }
            }
        }
    }

    // epilogue: divide by l, write ctx fp16 (b,s,h,d)
    #pragma unroll
    for (int hh = 0; hh < 2; hh++) {
        float inv = 1.0f / lrow[hh];
        int row = q0 + wm + lq + 8 * hh;
        size_t base = (((size_t)b * SS + row) * NH + h) * HD;
        #pragma unroll
        for (int nt = 0; nt < 16; nt++) {
            int d = nt * 8 + 2 * lr;
            __half2 vv = __floats2half2_rn(o[nt][2 * hh] * inv, o[nt][2 * hh + 1] * inv);
            *(__half2*)&ctx[base + d] = vv;
        }
    }
}

// ---------------- launch ----------------
extern "C" void kernel_launch(void* const* d_in, const int* in_sizes, int n_in,
                              void* d_out, int out_size)
{
    const float* x       = (const float*)d_in[0];
    const float* cosb    = (const float*)d_in[2];
    const float* sinb    = (const float*)d_in[3];
    const float* Wq      = (const float*)d_in[4];
    const float* Wk      = (const float*)d_in[5];
    const float* Wv      = (const float*)d_in[6];
    const float* Wo      = (const float*)d_in[7];
    const float* q_scale = (const float*)d_in[8];
    const float* k_scale = (const float*)d_in[9];
    float* out = (float*)d_out;

    float *q, *k, *v;
    cudaGetSymbolAddress((void**)&q, g_q);
    cudaGetSymbolAddress((void**)&k, g_k);
    cudaGetSymbolAddress((void**)&v, g_v);
    __half *xh, *ch, *wqT, *wkT, *wvT, *woT;
    cudaGetSymbolAddress((void**)&xh,  g_xh);
    cudaGetSymbolAddress((void**)&ch,  g_ch);
    cudaGetSymbolAddress((void**)&wqT, g_wqT);
    cudaGetSymbolAddress((void**)&wkT, g_wkT);
    cudaGetSymbolAddress((void**)&wvT, g_wvT);
    cudaGetSymbolAddress((void**)&woT, g_woT);

    const int M = BB * SS;   // 4096

    // preprocessing
    transpose_f16<<<dim3((NH * HD) / 32, DIN / 32), 256>>>(Wq, wqT, DIN, NH * HD);
    transpose_f16<<<dim3((NKV * HD) / 32, DIN / 32), 256>>>(Wk, wkT, DIN, NKV * HD);
    transpose_f16<<<dim3((NKV * HD) / 32, DIN / 32), 256>>>(Wv, wvT, DIN, NKV * HD);
    transpose_f16<<<dim3(DIN / 32, (NH * HD) / 32), 256>>>(Wo, woT, NH * HD, DIN);
    convert_f16<<<M * DIN / 8 / 256, 256>>>(x, xh, M * DIN);

    // projections (fp16 mma, fp32 out)
    cudaFuncSetAttribute(gemm_f16s, cudaFuncAttributeMaxDynamicSharedMemorySize,
                         GEMM_SMEM_BYTES);
    gemm_f16s<<<dim3((NH * HD) / 128, M / 128), 256, GEMM_SMEM_BYTES>>>(
        xh, wqT, q, M, NH * HD, DIN);
    gemm_f16s<<<dim3((NKV * HD) / 128, M / 128), 256, GEMM_SMEM_BYTES>>>(
        xh, wkT, k, M, NKV * HD, DIN);
    gemm_f16s<<<dim3((NKV * HD) / 128, M / 128), 256, GEMM_SMEM_BYTES>>>(
        xh, wvT, v, M, NKV * HD, DIN);

    // rmsnorm + rope (fp32)
    norm_rope_kernel<<<BB * SS * NH,  128>>>(q, cosb, sinb, q_scale, NH,  SCALING);
    norm_rope_kernel<<<BB * SS * NKV, 128>>>(k, cosb, sinb, k_scale, NKV, 1.0f);

    // attention (fp16 S + tf32 PV, 64 q/CTA, 2 CTAs/SM), writes fp16 ctx
    cudaFuncSetAttribute(attn_hyb, cudaFuncAttributeMaxDynamicSharedMemorySize,
                         ATT_SMEM_BYTES);
    attn_hyb<<<dim3(SS / 64, NH, BB), 128, ATT_SMEM_BYTES>>>(q, k, v, ch);

    // output projection (fp16 ctx -> fp32 out)
    gemm_f16s<<<dim3(DIN / 128, M / 128), 256, GEMM_SMEM_BYTES>>>(
        ch, woT, out, M, DIN, DIN);
}

// round 14
// speedup vs baseline: 4.7828x; 1.0480x over previous
#include <cuda_runtime.h>
#include <cuda_fp16.h>
#include <math.h>
#include <stdint.h>

#define BB   2
#define SS   2048
#define DIN  2048
#define NH   16
#define NKV  4
#define HD   128
#define GRP  4          // NH / NKV
#define SCALING 0.0625f // 256^-0.5
#define EPS  1e-6f

// ---------------- scratch (allocation-free: __device__ globals) ----------------
__device__ float g_q  [BB*SS*NH *HD];   // fp32 (b, s, h, d)
__device__ float g_k  [BB*SS*NKV*HD];
__device__ float g_v  [BB*SS*NKV*HD];
__device__ __half g_xh [BB*SS*DIN];     // x fp16 [M][K]
__device__ __half g_ch [BB*SS*NH*HD];   // ctx fp16 [M][K] (written by attention)
__device__ __half g_wqT[DIN*NH*HD];     // [N][K] fp16 transposed weights
__device__ __half g_wkT[DIN*NKV*HD];
__device__ __half g_wvT[DIN*NKV*HD];
__device__ __half g_woT[DIN*NH*HD];

// ================= mma =================
#define MMA_F16(C0,C1,C2,C3, A0,A1,A2,A3, B0,B1)                               \
    asm volatile("mma.sync.aligned.m16n8k16.row.col.f32.f16.f16.f32 "          \
                 "{%0,%1,%2,%3},{%4,%5,%6,%7},{%8,%9},{%0,%1,%2,%3};"          \
                 : "+f"(C0), "+f"(C1), "+f"(C2), "+f"(C3)                      \
                 : "r"(A0), "r"(A1), "r"(A2), "r"(A3), "r"(B0), "r"(B1))

// ================= preprocessing =================
__global__ __launch_bounds__(256)
void transpose_f16(const float* __restrict__ W, __half* __restrict__ T, int K, int N)
{
    __shared__ float t[32][33];
    const int tx = threadIdx.x & 31, ty = threadIdx.x >> 5;
    const int kb = blockIdx.y * 32, nb = blockIdx.x * 32;
    #pragma unroll
    for (int i = 0; i < 4; i++)
        t[ty + i * 8][tx] = W[(size_t)(kb + ty + i * 8) * N + nb + tx];
    __syncthreads();
    #pragma unroll
    for (int i = 0; i < 4; i++)
        T[(size_t)(nb + ty + i * 8) * K + kb + tx] = __float2half(t[tx][ty + i * 8]);
}

__global__ __launch_bounds__(256)
void convert_f16(const float* __restrict__ X, __half* __restrict__ H, int n)
{
    int i = (blockIdx.x * 256 + threadIdx.x) * 8;
    if (i < n) {
        float4 a = *(const float4*)&X[i];
        float4 b = *(const float4*)&X[i + 4];
        __half2 h0 = __floats2half2_rn(a.x, a.y);
        __half2 h1 = __floats2half2_rn(a.z, a.w);
        __half2 h2 = __floats2half2_rn(b.x, b.y);
        __half2 h3 = __floats2half2_rn(b.z, b.w);
        *(uint4*)&H[i] = make_uint4(*(uint32_t*)&h0, *(uint32_t*)&h1,
                                    *(uint32_t*)&h2, *(uint32_t*)&h3);
    }
}

// ================= fp16 GEMM (R10 verbatim, proven) =================
#define GW 36
#define GTILE (128 * GW)
#define GEMM_SMEM_BYTES (4 * GTILE * 4)    // 73728 B

__global__ __launch_bounds__(256)
void gemm_f16s(const __half* __restrict__ A, const __half* __restrict__ B,
               float* __restrict__ C, int M, int N, int K)
{
    extern __shared__ uint32_t sg[];
    const int tid  = threadIdx.x;
    const int lane = tid & 31;
    const int warp = tid >> 5;
    const int wm   = (warp >> 2) * 64;
    const int wn   = (warp & 3) * 32;
    const int m0   = blockIdx.y * 128;
    const int n0   = blockIdx.x * 128;
    const int lq   = lane >> 2, lr = lane & 3;

    const int srow = tid >> 1;
    const int sh   = (tid & 1) * 32;
    const __half* Ap = A + (size_t)(m0 + srow) * K + sh;
    const __half* Bp = B + (size_t)(n0 + srow) * K + sh;
    const uint32_t wst = srow * GW + (tid & 1) * 16;

    float c[4][4][4];
    #pragma unroll
    for (int mt = 0; mt < 4; mt++)
        #pragma unroll
        for (int nt = 0; nt < 4; nt++)
            #pragma unroll
            for (int e = 0; e < 4; e++) c[mt][nt][e] = 0.f;

    const int KT = K >> 6;

    #pragma unroll
    for (int i = 0; i < 4; i++) {
        *(uint4*)&sg[0 * GTILE + wst + i * 4] = *(const uint4*)(Ap + i * 8);
        *(uint4*)&sg[1 * GTILE + wst + i * 4] = *(const uint4*)(Bp + i * 8);
    }
    __syncthreads();

    int buf = 0;
    for (int kt = 0; kt < KT; kt++) {
        uint4 ra[4], rb[4];
        const bool has_next = (kt + 1 < KT);
        if (has_next) {
            const __half* ap = Ap + (size_t)(kt + 1) * 64;
            const __half* bp = Bp + (size_t)(kt + 1) * 64;
            #pragma unroll
            for (int i = 0; i < 4; i++) {
                ra[i] = *(const uint4*)(ap + i * 8);
                rb[i] = *(const uint4*)(bp + i * 8);
            }
        }

        const uint32_t* As = sg + buf * 2 * GTILE;
        const uint32_t* Bs = As + GTILE;
        #pragma unroll
        for (int ks = 0; ks < 4; ks++) {
            const int kw0 = ks * 8;
            uint32_t af[4][4], bf[4][2];
            #pragma unroll
            for (int mt = 0; mt < 4; mt++) {
                const uint32_t* p = &As[(wm + mt * 16 + lq) * GW + kw0 + lr];
                af[mt][0] = p[0];
                af[mt][1] = p[8 * GW];
                af[mt][2] = p[4];
                af[mt][3] = p[8 * GW + 4];
            }
            #pragma unroll
            for (int nt = 0; nt < 4; nt++) {
                const uint32_t* p = &Bs[(wn + nt * 8 + lq) * GW + kw0 + lr];
                bf[nt][0] = p[0];
                bf[nt][1] = p[4];
            }
            #pragma unroll
            for (int mt = 0; mt < 4; mt++)
                #pragma unroll
                for (int nt = 0; nt < 4; nt++)
                    MMA_F16(c[mt][nt][0], c[mt][nt][1], c[mt][nt][2], c[mt][nt][3],
                            af[mt][0], af[mt][1], af[mt][2], af[mt][3],
                            bf[nt][0], bf[nt][1]);
        }

        if (has_next) {
            uint32_t* dst = sg + (buf ^ 1) * 2 * GTILE;
            #pragma unroll
            for (int i = 0; i < 4; i++) {
                *(uint4*)&dst[wst + i * 4]         = ra[i];
                *(uint4*)&dst[GTILE + wst + i * 4] = rb[i];
            }
            __syncthreads();
            buf ^= 1;
        }
    }

    #pragma unroll
    for (int mt = 0; mt < 4; mt++) {
        #pragma unroll
        for (int nt = 0; nt < 4; nt++) {
            int r  = m0 + wm + mt * 16 + lq;
            int cc = n0 + wn + nt * 8 + 2 * lr;
            *(float2*)&C[(size_t)r * N + cc]       = make_float2(c[mt][nt][0], c[mt][nt][1]);
            *(float2*)&C[(size_t)(r + 8) * N + cc] = make_float2(c[mt][nt][2], c[mt][nt][3]);
        }
    }
}

// ---------------- RMSNorm + RoPE, fp32 in place (proven) ----------------
__global__ __launch_bounds__(128)
void norm_rope_kernel(float* __restrict__ data,
                      const float* __restrict__ cosb, const float* __restrict__ sinb,
                      const float* __restrict__ scale, int heads, float extra_scale)
{
    const int r = blockIdx.x;
    const int s = (r / heads) % SS;
    const int d = threadIdx.x;
    float* row = data + (size_t)r * HD;

    float val = row[d];
    float sq = val * val;
    #pragma unroll
    for (int off = 16; off; off >>= 1)
        sq += __shfl_xor_sync(0xffffffffu, sq, off);

    __shared__ float red[4];
    if ((d & 31) == 0) red[d >> 5] = sq;
    __syncthreads();
    float ss = red[0] + red[1] + red[2] + red[3];
    float rinv = rsqrtf(ss * (1.0f / HD) + EPS);
    float nrm = val * rinv * scale[d];

    __shared__ float buf[HD];
    buf[d] = nrm;
    __syncthreads();
    float partner = (d < HD / 2) ? -buf[d + HD / 2] : buf[d - HD / 2];
    float out = nrm * cosb[(size_t)s * HD + d] + partner * sinb[(size_t)s * HD + d];
    row[d] = out * extra_scale;
}

// ================= causal flash attention (all-fp16 MMA) =================
// 64 q-rows/CTA, 128 threads (4 warps x 16 q-rows), 64-key tiles.
// Q/K fp16 [row][d] (stride 68 words = 128 halves + pad).
// V fp16 TRANSPOSED [d][j] (stride 36 words = 64 halves + pad) so the PV
// B-fragment is the proven pv[0]/pv[4] pattern.
// P fp16 [row][j] (stride 36) so the PV A-fragment is the proven Q-pattern.
// smem 62464 B -> 3 CTAs/SM.
#define QH_STR 68
#define VT_STR 36
#define PS_STR 36
#define QS_OFF 0
#define KS_OFF (64 * QH_STR)            // 4352
#define VT_OFF (KS_OFF + 64 * QH_STR)   // 8704
#define PS_OFF (VT_OFF + 128 * VT_STR)  // 13312
#define ATT_SMEM_U32 (PS_OFF + 64 * PS_STR)    // 15616
#define ATT_SMEM_BYTES (ATT_SMEM_U32 * 4)      // 62464

__global__ __launch_bounds__(128)
void attn_hyb(const float* __restrict__ q, const float* __restrict__ k,
              const float* __restrict__ v, __half* __restrict__ ctx)
{
    extern __shared__ uint32_t sm[];
    uint32_t* Qs = sm + QS_OFF;
    uint32_t* Ks = sm + KS_OFF;
    uint32_t* Vt = sm + VT_OFF;
    uint32_t* Ps = sm + PS_OFF;

    const int qb = blockIdx.x, h = blockIdx.y, b = blockIdx.z;
    const int kvh = h / GRP;
    const int q0 = qb * 64;
    const int tid = threadIdx.x;
    const int lane = tid & 31;
    const int warp = tid >> 5;       // 0..3
    const int wm = warp * 16;
    const int lq = lane >> 2;
    const int lr = lane & 3;

    // Q tile: 64 rows x 32 tasks; task = 4 floats -> 2 fp16 words. (proven)
    for (int idx = tid; idx < 64 * 32; idx += 128) {
        int i  = idx >> 5;
        int c4 = idx & 31;
        float4 vq = *(const float4*)&q[((((size_t)b * SS + q0 + i) * NH) + h) * HD + c4 * 4];
        __half2 h0 = __floats2half2_rn(vq.x, vq.y);
        __half2 h1 = __floats2half2_rn(vq.z, vq.w);
        *(uint2*)&Qs[i * QH_STR + c4 * 2] = make_uint2(*(uint32_t*)&h0, *(uint32_t*)&h1);
    }

    float o[16][4];
    #pragma unroll
    for (int nt = 0; nt < 16; nt++)
        #pragma unroll
        for (int e = 0; e < 4; e++) o[nt][e] = 0.f;
    float mrow[2] = {-1e30f, -1e30f};
    float lrow[2] = {0.f, 0.f};

    for (int kb = 0; kb <= qb; kb++) {
        const int k0 = kb * 64;
        __syncthreads();   // prev iter done reading; Q stores visible (iter 0)

        // K fp16 [j][d] (proven pattern)
        for (int idx = tid; idx < 64 * 32; idx += 128) {
            int j  = idx >> 5;
            int c4 = idx & 31;
            float4 vk = *(const float4*)&k[(((size_t)b * SS + k0 + j) * NKV + kvh) * HD + c4 * 4];
            __half2 h0 = __floats2half2_rn(vk.x, vk.y);
            __half2 h1 = __floats2half2_rn(vk.z, vk.w);
            *(uint2*)&Ks[j * QH_STR + c4 * 2] = make_uint2(*(uint32_t*)&h0, *(uint32_t*)&h1);
        }
        // V fp16 TRANSPOSED [d][j]: task = (d, jw), packs j=2jw (lo), 2jw+1 (hi).
        // Consecutive threads cover consecutive d -> coalesced 512B gmem reads.
        for (int idx = tid; idx < 128 * 32; idx += 128) {
            int d  = idx & 127;
            int jw = idx >> 7;            // 0..31
            size_t r0 = (((size_t)b * SS + k0 + 2 * jw)     * NKV + kvh) * HD + d;
            size_t r1 = (((size_t)b * SS + k0 + 2 * jw + 1) * NKV + kvh) * HD + d;
            __half2 hv = __floats2half2_rn(v[r0], v[r1]);
            Vt[d * VT_STR + jw] = *(uint32_t*)&hv;
        }
        __syncthreads();

        const bool active = (k0 <= q0 + wm + 15);
        if (active) {
            // ---- S = Q K^T (fp16, 8 k16-steps over HD=128 halves) ----
            float s[8][4];
            #pragma unroll
            for (int nt = 0; nt < 8; nt++)
                #pragma unroll
                for (int e = 0; e < 4; e++) s[nt][e] = 0.f;

            #pragma unroll
            for (int ks = 0; ks < 8; ks++) {
                const int kw0 = ks * 8;
                uint32_t af[4];
                const uint32_t* pq = &Qs[(wm + lq) * QH_STR + kw0 + lr];
                af[0] = pq[0];
                af[1] = pq[8 * QH_STR];
                af[2] = pq[4];
                af[3] = pq[8 * QH_STR + 4];
                #pragma unroll
                for (int nt = 0; nt < 8; nt++) {
                    const uint32_t* pk = &Ks[(nt * 8 + lq) * QH_STR + kw0 + lr];
                    MMA_F16(s[nt][0], s[nt][1], s[nt][2], s[nt][3],
                            af[0], af[1], af[2], af[3], pk[0], pk[4]);
                }
            }

            // causal mask on the diagonal tile
            if (kb == qb) {
                int i0 = q0 + wm + lq;
                #pragma unroll
                for (int nt = 0; nt < 8; nt++) {
                    int j0 = k0 + nt * 8 + 2 * lr;
                    if (j0     > i0)     s[nt][0] = -1e30f;
                    if (j0 + 1 > i0)     s[nt][1] = -1e30f;
                    if (j0     > i0 + 8) s[nt][2] = -1e30f;
                    if (j0 + 1 > i0 + 8) s[nt][3] = -1e30f;
                }
            }

            // ---- online softmax; P written as packed fp16 words ----
            #pragma unroll
            for (int hh = 0; hh < 2; hh++) {
                float rmax = -1e30f;
                #pragma unroll
                for (int nt = 0; nt < 8; nt++)
                    rmax = fmaxf(rmax, fmaxf(s[nt][2 * hh], s[nt][2 * hh + 1]));
                rmax = fmaxf(rmax, __shfl_xor_sync(0xffffffffu, rmax, 1));
                rmax = fmaxf(rmax, __shfl_xor_sync(0xffffffffu, rmax, 2));

                float mnew  = fmaxf(mrow[hh], rmax);
                float alpha = __expf(mrow[hh] - mnew);
                mrow[hh] = mnew;

                float rsum = 0.f;
                int prow = (wm + lq + 8 * hh) * PS_STR;
                #pragma unroll
                for (int nt = 0; nt < 8; nt++) {
                    float p0 = __expf(s[nt][2 * hh]     - mnew);
                    float p1 = __expf(s[nt][2 * hh + 1] - mnew);
                    rsum += p0 + p1;
                    __half2 hp = __floats2half2_rn(p0, p1);
                    Ps[prow + nt * 4 + lr] = *(uint32_t*)&hp;   // word (nt*8+2lr)/2
                }
                rsum += __shfl_xor_sync(0xffffffffu, rsum, 1);
                rsum += __shfl_xor_sync(0xffffffffu, rsum, 2);
                lrow[hh] = lrow[hh] * alpha + rsum;

                #pragma unroll
                for (int nt = 0; nt < 16; nt++) {
                    o[nt][2 * hh]     *= alpha;
                    o[nt][2 * hh + 1] *= alpha;
                }
            }
            __syncwarp();

            // ---- O += P V (fp16, 4 k16-steps over j=64) ----
            #pragma unroll
            for (int ks = 0; ks < 4; ks++) {
                const int kw0 = ks * 8;
                uint32_t af[4];
                const uint32_t* pp = &Ps[(wm + lq) * PS_STR + kw0 + lr];
                af[0] = pp[0];
                af[1] = pp[8 * PS_STR];
                af[2] = pp[4];
                af[3] = pp[8 * PS_STR + 4];
                #pragma unroll
                for (int nt = 0; nt < 16; nt++) {
                    const uint32_t* pv = &Vt[(nt * 8 + lq) * VT_STR + kw0 + lr];
                    MMA_F16(o[nt][0], o[nt][1], o[nt][2], o[nt][3],
                            af[0], af[1], af[2], af[3], pv[0], pv[4]);
                }
            }
        }
    }

    // epilogue: divide by l, write ctx fp16 (b,s,h,d)
    #pragma unroll
    for (int hh = 0; hh < 2; hh++) {
        float inv = 1.0f / lrow[hh];
        int row = q0 + wm + lq + 8 * hh;
        size_t base = (((size_t)b * SS + row) * NH + h) * HD;
        #pragma unroll
        for (int nt = 0; nt < 16; nt++) {
            int d = nt * 8 + 2 * lr;
            __half2 vv = __floats2half2_rn(o[nt][2 * hh] * inv, o[nt][2 * hh + 1] * inv);
            *(__half2*)&ctx[base + d] = vv;
        }
    }
}

// ---------------- launch ----------------
extern "C" void kernel_launch(void* const* d_in, const int* in_sizes, int n_in,
                              void* d_out, int out_size)
{
    const float* x       = (const float*)d_in[0];
    const float* cosb    = (const float*)d_in[2];
    const float* sinb    = (const float*)d_in[3];
    const float* Wq      = (const float*)d_in[4];
    const float* Wk      = (const float*)d_in[5];
    const float* Wv      = (const float*)d_in[6];
    const float* Wo      = (const float*)d_in[7];
    const float* q_scale = (const float*)d_in[8];
    const float* k_scale = (const float*)d_in[9];
    float* out = (float*)d_out;

    float *q, *k, *v;
    cudaGetSymbolAddress((void**)&q, g_q);
    cudaGetSymbolAddress((void**)&k, g_k);
    cudaGetSymbolAddress((void**)&v, g_v);
    __half *xh, *ch, *wqT, *wkT, *wvT, *woT;
    cudaGetSymbolAddress((void**)&xh,  g_xh);
    cudaGetSymbolAddress((void**)&ch,  g_ch);
    cudaGetSymbolAddress((void**)&wqT, g_wqT);
    cudaGetSymbolAddress((void**)&wkT, g_wkT);
    cudaGetSymbolAddress((void**)&wvT, g_wvT);
    cudaGetSymbolAddress((void**)&woT, g_woT);

    const int M = BB * SS;   // 4096

    // preprocessing
    transpose_f16<<<dim3((NH * HD) / 32, DIN / 32), 256>>>(Wq, wqT, DIN, NH * HD);
    transpose_f16<<<dim3((NKV * HD) / 32, DIN / 32), 256>>>(Wk, wkT, DIN, NKV * HD);
    transpose_f16<<<dim3((NKV * HD) / 32, DIN / 32), 256>>>(Wv, wvT, DIN, NKV * HD);
    transpose_f16<<<dim3(DIN / 32, (NH * HD) / 32), 256>>>(Wo, woT, NH * HD, DIN);
    convert_f16<<<M * DIN / 8 / 256, 256>>>(x, xh, M * DIN);

    // projections (fp16 mma, fp32 out)
    cudaFuncSetAttribute(gemm_f16s, cudaFuncAttributeMaxDynamicSharedMemorySize,
                         GEMM_SMEM_BYTES);
    gemm_f16s<<<dim3((NH * HD) / 128, M / 128), 256, GEMM_SMEM_BYTES>>>(
        xh, wqT, q, M, NH * HD, DIN);
    gemm_f16s<<<dim3((NKV * HD) / 128, M / 128), 256, GEMM_SMEM_BYTES>>>(
        xh, wkT, k, M, NKV * HD, DIN);
    gemm_f16s<<<dim3((NKV * HD) / 128, M / 128), 256, GEMM_SMEM_BYTES>>>(
        xh, wvT, v, M, NKV * HD, DIN);

    // rmsnorm + rope (fp32)
    norm_rope_kernel<<<BB * SS * NH,  128>>>(q, cosb, sinb, q_scale, NH,  SCALING);
    norm_rope_kernel<<<BB * SS * NKV, 128>>>(k, cosb, sinb, k_scale, NKV, 1.0f);

    // attention (all-fp16 MMA, 64 q/CTA, 3 CTAs/SM), writes fp16 ctx
    cudaFuncSetAttribute(attn_hyb, cudaFuncAttributeMaxDynamicSharedMemorySize,
                         ATT_SMEM_BYTES);
    attn_hyb<<<dim3(SS / 64, NH, BB), 128, ATT_SMEM_BYTES>>>(q, k, v, ch);

    // output projection (fp16 ctx -> fp32 out)
    gemm_f16s<<<dim3(DIN / 128, M / 128), 256, GEMM_SMEM_BYTES>>>(
        ch, woT, out, M, DIN, DIN);
}

// round 15
// speedup vs baseline: 5.2535x; 1.0984x over previous
#include <cuda_runtime.h>
#include <cuda_fp16.h>
#include <math.h>
#include <stdint.h>

#define BB   2
#define SS   2048
#define DIN  2048
#define NH   16
#define NKV  4
#define HD   128
#define GRP  4          // NH / NKV
#define SCALING 0.0625f // 256^-0.5
#define EPS  1e-6f

// ---------------- scratch (allocation-free: __device__ globals) ----------------
__device__ float g_q  [BB*SS*NH *HD];   // fp32 (b, s, h, d)
__device__ float g_k  [BB*SS*NKV*HD];
__device__ float g_v  [BB*SS*NKV*HD];
__device__ __half g_xh [BB*SS*DIN];     // x fp16 [M][K]
__device__ __half g_ch [BB*SS*NH*HD];   // ctx fp16 [M][K] (written by attention)
__device__ __half g_wqT[DIN*NH*HD];     // [N][K] fp16 transposed weights
__device__ __half g_wkT[DIN*NKV*HD];
__device__ __half g_wvT[DIN*NKV*HD];
__device__ __half g_woT[DIN*NH*HD];

// ================= mma / helpers =================
__device__ __forceinline__ uint32_t smem_u32(const void* p) {
    uint32_t a;
    asm("{ .reg .u64 t; cvta.to.shared.u64 t, %1; cvt.u32.u64 %0, t; }" : "=r"(a) : "l"(p));
    return a;
}
#define MMA_F16(C0,C1,C2,C3, A0,A1,A2,A3, B0,B1)                               \
    asm volatile("mma.sync.aligned.m16n8k16.row.col.f32.f16.f16.f32 "          \
                 "{%0,%1,%2,%3},{%4,%5,%6,%7},{%8,%9},{%0,%1,%2,%3};"          \
                 : "+f"(C0), "+f"(C1), "+f"(C2), "+f"(C3)                      \
                 : "r"(A0), "r"(A1), "r"(A2), "r"(A3), "r"(B0), "r"(B1))
#define LDSM_X4(R0,R1,R2,R3, ADDR)                                             \
    asm volatile("ldmatrix.sync.aligned.m8n8.x4.shared.b16 {%0,%1,%2,%3}, [%4];" \
        : "=r"(R0), "=r"(R1), "=r"(R2), "=r"(R3) : "r"(ADDR))

// ================= preprocessing =================
__global__ __launch_bounds__(256)
void transpose_f16(const float* __restrict__ W, __half* __restrict__ T, int K, int N)
{
    __shared__ float t[32][33];
    const int tx = threadIdx.x & 31, ty = threadIdx.x >> 5;
    const int kb = blockIdx.y * 32, nb = blockIdx.x * 32;
    #pragma unroll
    for (int i = 0; i < 4; i++)
        t[ty + i * 8][tx] = W[(size_t)(kb + ty + i * 8) * N + nb + tx];
    __syncthreads();
    #pragma unroll
    for (int i = 0; i < 4; i++)
        T[(size_t)(nb + ty + i * 8) * K + kb + tx] = __float2half(t[tx][ty + i * 8]);
}

__global__ __launch_bounds__(256)
void convert_f16(const float* __restrict__ X, __half* __restrict__ H, int n)
{
    int i = (blockIdx.x * 256 + threadIdx.x) * 8;
    if (i < n) {
        float4 a = *(const float4*)&X[i];
        float4 b = *(const float4*)&X[i + 4];
        __half2 h0 = __floats2half2_rn(a.x, a.y);
        __half2 h1 = __floats2half2_rn(a.z, a.w);
        __half2 h2 = __floats2half2_rn(b.x, b.y);
        __half2 h3 = __floats2half2_rn(b.z, b.w);
        *(uint4*)&H[i] = make_uint4(*(uint32_t*)&h0, *(uint32_t*)&h1,
                                    *(uint32_t*)&h2, *(uint32_t*)&h3);
    }
}

// ================= fp16 GEMM: C[M,N] = A[M,K] * B[N,K]^T =================
// Same tiling/staging as the proven R10 kernel; fragment loads switched from
// 24 scalar LDS to 6 ldmatrix.x4 per k16-step. Lane map derived from the
// proven scalar pattern:
//   A matrices {(r,klo),(r+8,klo),(r,khi),(r+8,khi)} = {a0,a1,a2,a3}
//     -> row = lane&15, k-half-off = (lane>>4)*8
//   B matrices {(nt0,klo),(nt0,khi),(nt1,klo),(nt1,khi)} = {b0,b1,b0',b1'}
//     -> row = lane&7, k-half-off = ((lane>>3)&1)*8, nt-pair = lane>>4
// Banks: stride 36 words -> row r starts at bank 4r mod 32; 8 rows/phase
// hit 8 distinct bank groups -> conflict-free.
#define GW 36
#define GTILE (128 * GW)
#define GEMM_SMEM_BYTES (4 * GTILE * 4)    // 73728 B

__global__ __launch_bounds__(256)
void gemm_f16s(const __half* __restrict__ A, const __half* __restrict__ B,
               float* __restrict__ C, int M, int N, int K)
{
    extern __shared__ uint32_t sg[];
    const uint32_t sbase = smem_u32(sg);
    const int tid  = threadIdx.x;
    const int lane = tid & 31;
    const int warp = tid >> 5;
    const int wm   = (warp >> 2) * 64;
    const int wn   = (warp & 3) * 32;
    const int m0   = blockIdx.y * 128;
    const int n0   = blockIdx.x * 128;
    const int lq   = lane >> 2, lr = lane & 3;

    const int srow = tid >> 1;
    const int sh   = (tid & 1) * 32;
    const __half* Ap = A + (size_t)(m0 + srow) * K + sh;
    const __half* Bp = B + (size_t)(n0 + srow) * K + sh;
    const uint32_t wst = srow * GW + (tid & 1) * 16;

    // ldmatrix per-lane byte offsets
    const uint32_t a_lane = (((lane & 15) + wm) * GW + (lane >> 4) * 4) * 4;
    const uint32_t b_lane = (((lane & 7) + wn + (lane >> 4) * 8) * GW
                             + ((lane >> 3) & 1) * 4) * 4;

    float c[4][4][4];
    #pragma unroll
    for (int mt = 0; mt < 4; mt++)
        #pragma unroll
        for (int nt = 0; nt < 4; nt++)
            #pragma unroll
            for (int e = 0; e < 4; e++) c[mt][nt][e] = 0.f;

    const int KT = K >> 6;

    #pragma unroll
    for (int i = 0; i < 4; i++) {
        *(uint4*)&sg[0 * GTILE + wst + i * 4] = *(const uint4*)(Ap + i * 8);
        *(uint4*)&sg[1 * GTILE + wst + i * 4] = *(const uint4*)(Bp + i * 8);
    }
    __syncthreads();

    int buf = 0;
    for (int kt = 0; kt < KT; kt++) {
        uint4 ra[4], rb[4];
        const bool has_next = (kt + 1 < KT);
        if (has_next) {
            const __half* ap = Ap + (size_t)(kt + 1) * 64;
            const __half* bp = Bp + (size_t)(kt + 1) * 64;
            #pragma unroll
            for (int i = 0; i < 4; i++) {
                ra[i] = *(const uint4*)(ap + i * 8);
                rb[i] = *(const uint4*)(bp + i * 8);
            }
        }

        const uint32_t abase = sbase + (uint32_t)(buf * 2 * GTILE) * 4;
        const uint32_t bbase = abase + (uint32_t)GTILE * 4;
        #pragma unroll
        for (int ks = 0; ks < 4; ks++) {
            const uint32_t koff = (uint32_t)(ks * 8) * 4;   // 8 words = 16 halves
            uint32_t af[4][4], bf[2][4];
            #pragma unroll
            for (int mt = 0; mt < 4; mt++)
                LDSM_X4(af[mt][0], af[mt][1], af[mt][2], af[mt][3],
                        abase + (uint32_t)(mt * 16 * GW) * 4 + koff + a_lane);
            #pragma unroll
            for (int t = 0; t < 2; t++)
                LDSM_X4(bf[t][0], bf[t][1], bf[t][2], bf[t][3],
                        bbase + (uint32_t)(t * 16 * GW) * 4 + koff + b_lane);
            #pragma unroll
            for (int mt = 0; mt < 4; mt++)
                #pragma unroll
                for (int nt = 0; nt < 4; nt++)
                    MMA_F16(c[mt][nt][0], c[mt][nt][1], c[mt][nt][2], c[mt][nt][3],
                            af[mt][0], af[mt][1], af[mt][2], af[mt][3],
                            bf[nt >> 1][(nt & 1) * 2], bf[nt >> 1][(nt & 1) * 2 + 1]);
        }

        if (has_next) {
            uint32_t* dst = sg + (buf ^ 1) * 2 * GTILE;
            #pragma unroll
            for (int i = 0; i < 4; i++) {
                *(uint4*)&dst[wst + i * 4]         = ra[i];
                *(uint4*)&dst[GTILE + wst + i * 4] = rb[i];
            }
            __syncthreads();
            buf ^= 1;
        }
    }

    #pragma unroll
    for (int mt = 0; mt < 4; mt++) {
        #pragma unroll
        for (int nt = 0; nt < 4; nt++) {
            int r  = m0 + wm + mt * 16 + lq;
            int cc = n0 + wn + nt * 8 + 2 * lr;
            *(float2*)&C[(size_t)r * N + cc]       = make_float2(c[mt][nt][0], c[mt][nt][1]);
            *(float2*)&C[(size_t)(r + 8) * N + cc] = make_float2(c[mt][nt][2], c[mt][nt][3]);
        }
    }
}

// ---------------- RMSNorm + RoPE, fp32 in place (proven) ----------------
__global__ __launch_bounds__(128)
void norm_rope_kernel(float* __restrict__ data,
                      const float* __restrict__ cosb, const float* __restrict__ sinb,
                      const float* __restrict__ scale, int heads, float extra_scale)
{
    const int r = blockIdx.x;
    const int s = (r / heads) % SS;
    const int d = threadIdx.x;
    float* row = data + (size_t)r * HD;

    float val = row[d];
    float sq = val * val;
    #pragma unroll
    for (int off = 16; off; off >>= 1)
        sq += __shfl_xor_sync(0xffffffffu, sq, off);

    __shared__ float red[4];
    if ((d & 31) == 0) red[d >> 5] = sq;
    __syncthreads();
    float ss = red[0] + red[1] + red[2] + red[3];
    float rinv = rsqrtf(ss * (1.0f / HD) + EPS);
    float nrm = val * rinv * scale[d];

    __shared__ float buf[HD];
    buf[d] = nrm;
    __syncthreads();
    float partner = (d < HD / 2) ? -buf[d + HD / 2] : buf[d - HD / 2];
    float out = nrm * cosb[(size_t)s * HD + d] + partner * sinb[(size_t)s * HD + d];
    row[d] = out * extra_scale;
}

// ================= causal flash attention (R14 verbatim, proven) =================
#define QH_STR 68
#define VT_STR 36
#define PS_STR 36
#define QS_OFF 0
#define KS_OFF (64 * QH_STR)            // 4352
#define VT_OFF (KS_OFF + 64 * QH_STR)   // 8704
#define PS_OFF (VT_OFF + 128 * VT_STR)  // 13312
#define ATT_SMEM_U32 (PS_OFF + 64 * PS_STR)    // 15616
#define ATT_SMEM_BYTES (ATT_SMEM_U32 * 4)      // 62464

__global__ __launch_bounds__(128)
void attn_hyb(const float* __restrict__ q, const float* __restrict__ k,
              const float* __restrict__ v, __half* __restrict__ ctx)
{
    extern __shared__ uint32_t sm[];
    uint32_t* Qs = sm + QS_OFF;
    uint32_t* Ks = sm + KS_OFF;
    uint32_t* Vt = sm + VT_OFF;
    uint32_t* Ps = sm + PS_OFF;

    const int qb = blockIdx.x, h = blockIdx.y, b = blockIdx.z;
    const int kvh = h / GRP;
    const int q0 = qb * 64;
    const int tid = threadIdx.x;
    const int lane = tid & 31;
    const int warp = tid >> 5;       // 0..3
    const int wm = warp * 16;
    const int lq = lane >> 2;
    const int lr = lane & 3;

    for (int idx = tid; idx < 64 * 32; idx += 128) {
        int i  = idx >> 5;
        int c4 = idx & 31;
        float4 vq = *(const float4*)&q[((((size_t)b * SS + q0 + i) * NH) + h) * HD + c4 * 4];
        __half2 h0 = __floats2half2_rn(vq.x, vq.y);
        __half2 h1 = __floats2half2_rn(vq.z, vq.w);
        *(uint2*)&Qs[i * QH_STR + c4 * 2] = make_uint2(*(uint32_t*)&h0, *(uint32_t*)&h1);
    }

    float o[16][4];
    #pragma unroll
    for (int nt = 0; nt < 16; nt++)
        #pragma unroll
        for (int e = 0; e < 4; e++) o[nt][e] = 0.f;
    float mrow[2] = {-1e30f, -1e30f};
    float lrow[2] = {0.f, 0.f};

    for (int kb = 0; kb <= qb; kb++) {
        const int k0 = kb * 64;
        __syncthreads();

        for (int idx = tid; idx < 64 * 32; idx += 128) {
            int j  = idx >> 5;
            int c4 = idx & 31;
            float4 vk = *(const float4*)&k[(((size_t)b * SS + k0 + j) * NKV + kvh) * HD + c4 * 4];
            __half2 h0 = __floats2half2_rn(vk.x, vk.y);
            __half2 h1 = __floats2half2_rn(vk.z, vk.w);
            *(uint2*)&Ks[j * QH_STR + c4 * 2] = make_uint2(*(uint32_t*)&h0, *(uint32_t*)&h1);
        }
        for (int idx = tid; idx < 128 * 32; idx += 128) {
            int d  = idx & 127;
            int jw = idx >> 7;
            size_t r0 = (((size_t)b * SS + k0 + 2 * jw)     * NKV + kvh) * HD + d;
            size_t r1 = (((size_t)b * SS + k0 + 2 * jw + 1) * NKV + kvh) * HD + d;
            __half2 hv = __floats2half2_rn(v[r0], v[r1]);
            Vt[d * VT_STR + jw] = *(uint32_t*)&hv;
        }
        __syncthreads();

        const bool active = (k0 <= q0 + wm + 15);
        if (active) {
            float s[8][4];
            #pragma unroll
            for (int nt = 0; nt < 8; nt++)
                #pragma unroll
                for (int e = 0; e < 4; e++) s[nt][e] = 0.f;

            #pragma unroll
            for (int ks = 0; ks < 8; ks++) {
                const int kw0 = ks * 8;
                uint32_t af[4];
                const uint32_t* pq = &Qs[(wm + lq) * QH_STR + kw0 + lr];
                af[0] = pq[0];
                af[1] = pq[8 * QH_STR];
                af[2] = pq[4];
                af[3] = pq[8 * QH_STR + 4];
                #pragma unroll
                for (int nt = 0; nt < 8; nt++) {
                    const uint32_t* pk = &Ks[(nt * 8 + lq) * QH_STR + kw0 + lr];
                    MMA_F16(s[nt][0], s[nt][1], s[nt][2], s[nt][3],
                            af[0], af[1], af[2], af[3], pk[0], pk[4]);
                }
            }

            if (kb == qb) {
                int i0 = q0 + wm + lq;
                #pragma unroll
                for (int nt = 0; nt < 8; nt++) {
                    int j0 = k0 + nt * 8 + 2 * lr;
                    if (j0     > i0)     s[nt][0] = -1e30f;
                    if (j0 + 1 > i0)     s[nt][1] = -1e30f;
                    if (j0     > i0 + 8) s[nt][2] = -1e30f;
                    if (j0 + 1 > i0 + 8) s[nt][3] = -1e30f;
                }
            }

            #pragma unroll
            for (int hh = 0; hh < 2; hh++) {
                float rmax = -1e30f;
                #pragma unroll
                for (int nt = 0; nt < 8; nt++)
                    rmax = fmaxf(rmax, fmaxf(s[nt][2 * hh], s[nt][2 * hh + 1]));
                rmax = fmaxf(rmax, __shfl_xor_sync(0xffffffffu, rmax, 1));
                rmax = fmaxf(rmax, __shfl_xor_sync(0xffffffffu, rmax, 2));

                float mnew  = fmaxf(mrow[hh], rmax);
                float alpha = __expf(mrow[hh] - mnew);
                mrow[hh] = mnew;

                float rsum = 0.f;
                int prow = (wm + lq + 8 * hh) * PS_STR;
                #pragma unroll
                for (int nt = 0; nt < 8; nt++) {
                    float p0 = __expf(s[nt][2 * hh]     - mnew);
                    float p1 = __expf(s[nt][2 * hh + 1] - mnew);
                    rsum += p0 + p1;
                    __half2 hp = __floats2half2_rn(p0, p1);
                    Ps[prow + nt * 4 + lr] = *(uint32_t*)&hp;
                }
                rsum += __shfl_xor_sync(0xffffffffu, rsum, 1);
                rsum += __shfl_xor_sync(0xffffffffu, rsum, 2);
                lrow[hh] = lrow[hh] * alpha + rsum;

                #pragma unroll
                for (int nt = 0; nt < 16; nt++) {
                    o[nt][2 * hh]     *= alpha;
                    o[nt][2 * hh + 1] *= alpha;
                }
            }
            __syncwarp();

            #pragma unroll
            for (int ks = 0; ks < 4; ks++) {
                const int kw0 = ks * 8;
                uint32_t af[4];
                const uint32_t* pp = &Ps[(wm + lq) * PS_STR + kw0 + lr];
                af[0] = pp[0];
                af[1] = pp[8 * PS_STR];
                af[2] = pp[4];
                af[3] = pp[8 * PS_STR + 4];
                #pragma unroll
                for (int nt = 0; nt < 16; nt++) {
                    const uint32_t* pv = &Vt[(nt * 8 + lq) * VT_STR + kw0 + lr];
                    MMA_F16(o[nt][0], o[nt][1], o[nt][2], o[nt][3],
                            af[0], af[1], af[2], af[3], pv[0], pv[4]);
                }
            }
        }
    }

    #pragma unroll
    for (int hh = 0; hh < 2; hh++) {
        float inv = 1.0f / lrow[hh];
        int row = q0 + wm + lq + 8 * hh;
        size_t base = (((size_t)b * SS + row) * NH + h) * HD;
        #pragma unroll
        for (int nt = 0; nt < 16; nt++) {
            int d = nt * 8 + 2 * lr;
            __half2 vv = __floats2half2_rn(o[nt][2 * hh] * inv, o[nt][2 * hh + 1] * inv);
            *(__half2*)&ctx[base + d] = vv;
        }
    }
}

// ---------------- launch ----------------
extern "C" void kernel_launch(void* const* d_in, const int* in_sizes, int n_in,
                              void* d_out, int out_size)
{
    const float* x       = (const float*)d_in[0];
    const float* cosb    = (const float*)d_in[2];
    const float* sinb    = (const float*)d_in[3];
    const float* Wq      = (const float*)d_in[4];
    const float* Wk      = (const float*)d_in[5];
    const float* Wv      = (const float*)d_in[6];
    const float* Wo      = (const float*)d_in[7];
    const float* q_scale = (const float*)d_in[8];
    const float* k_scale = (const float*)d_in[9];
    float* out = (float*)d_out;

    float *q, *k, *v;
    cudaGetSymbolAddress((void**)&q, g_q);
    cudaGetSymbolAddress((void**)&k, g_k);
    cudaGetSymbolAddress((void**)&v, g_v);
    __half *xh, *ch, *wqT, *wkT, *wvT, *woT;
    cudaGetSymbolAddress((void**)&xh,  g_xh);
    cudaGetSymbolAddress((void**)&ch,  g_ch);
    cudaGetSymbolAddress((void**)&wqT, g_wqT);
    cudaGetSymbolAddress((void**)&wkT, g_wkT);
    cudaGetSymbolAddress((void**)&wvT, g_wvT);
    cudaGetSymbolAddress((void**)&woT, g_woT);

    const int M = BB * SS;   // 4096

    // preprocessing
    transpose_f16<<<dim3((NH * HD) / 32, DIN / 32), 256>>>(Wq, wqT, DIN, NH * HD);
    transpose_f16<<<dim3((NKV * HD) / 32, DIN / 32), 256>>>(Wk, wkT, DIN, NKV * HD);
    transpose_f16<<<dim3((NKV * HD) / 32, DIN / 32), 256>>>(Wv, wvT, DIN, NKV * HD);
    transpose_f16<<<dim3(DIN / 32, (NH * HD) / 32), 256>>>(Wo, woT, NH * HD, DIN);
    convert_f16<<<M * DIN / 8 / 256, 256>>>(x, xh, M * DIN);

    // projections (fp16 mma + ldmatrix, fp32 out)
    cudaFuncSetAttribute(gemm_f16s, cudaFuncAttributeMaxDynamicSharedMemorySize,
                         GEMM_SMEM_BYTES);
    gemm_f16s<<<dim3((NH * HD) / 128, M / 128), 256, GEMM_SMEM_BYTES>>>(
        xh, wqT, q, M, NH * HD, DIN);
    gemm_f16s<<<dim3((NKV * HD) / 128, M / 128), 256, GEMM_SMEM_BYTES>>>(
        xh, wkT, k, M, NKV * HD, DIN);
    gemm_f16s<<<dim3((NKV * HD) / 128, M / 128), 256, GEMM_SMEM_BYTES>>>(
        xh, wvT, v, M, NKV * HD, DIN);

    // rmsnorm + rope (fp32)
    norm_rope_kernel<<<BB * SS * NH,  128>>>(q, cosb, sinb, q_scale, NH,  SCALING);
    norm_rope_kernel<<<BB * SS * NKV, 128>>>(k, cosb, sinb, k_scale, NKV, 1.0f);

    // attention (all-fp16 MMA, 64 q/CTA, 3 CTAs/SM), writes fp16 ctx
    cudaFuncSetAttribute(attn_hyb, cudaFuncAttributeMaxDynamicSharedMemorySize,
                         ATT_SMEM_BYTES);
    attn_hyb<<<dim3(SS / 64, NH, BB), 128, ATT_SMEM_BYTES>>>(q, k, v, ch);

    // output projection (fp16 ctx -> fp32 out)
    gemm_f16s<<<dim3(DIN / 128, M / 128), 256, GEMM_SMEM_BYTES>>>(
        ch, woT, out, M, DIN, DIN);
}

// round 16
// speedup vs baseline: 5.3876x; 1.0255x over previous
#include <cuda_runtime.h>
#include <cuda_fp16.h>
#include <math.h>
#include <stdint.h>

#define BB   2
#define SS   2048
#define DIN  2048
#define NH   16
#define NKV  4
#define HD   128
#define GRP  4          // NH / NKV
#define SCALING 0.0625f // 256^-0.5
#define EPS  1e-6f

// ---------------- scratch (allocation-free: __device__ globals) ----------------
__device__ float g_q  [BB*SS*NH *HD];   // fp32 (b, s, h, d)
__device__ float g_k  [BB*SS*NKV*HD];
__device__ float g_v  [BB*SS*NKV*HD];
__device__ __half g_xh [BB*SS*DIN];     // x fp16 [M][K]
__device__ __half g_ch [BB*SS*NH*HD];   // ctx fp16 [M][K] (written by attention)
__device__ __half g_wqT[DIN*NH*HD];     // [N][K] fp16 transposed weights
__device__ __half g_wkT[DIN*NKV*HD];
__device__ __half g_wvT[DIN*NKV*HD];
__device__ __half g_woT[DIN*NH*HD];

// ================= mma / helpers =================
__device__ __forceinline__ uint32_t smem_u32(const void* p) {
    uint32_t a;
    asm("{ .reg .u64 t; cvta.to.shared.u64 t, %1; cvt.u32.u64 %0, t; }" : "=r"(a) : "l"(p));
    return a;
}
#define MMA_F16(C0,C1,C2,C3, A0,A1,A2,A3, B0,B1)                               \
    asm volatile("mma.sync.aligned.m16n8k16.row.col.f32.f16.f16.f32 "          \
                 "{%0,%1,%2,%3},{%4,%5,%6,%7},{%8,%9},{%0,%1,%2,%3};"          \
                 : "+f"(C0), "+f"(C1), "+f"(C2), "+f"(C3)                      \
                 : "r"(A0), "r"(A1), "r"(A2), "r"(A3), "r"(B0), "r"(B1))
#define LDSM_X4(R0,R1,R2,R3, ADDR)                                             \
    asm volatile("ldmatrix.sync.aligned.m8n8.x4.shared.b16 {%0,%1,%2,%3}, [%4];" \
        : "=r"(R0), "=r"(R1), "=r"(R2), "=r"(R3) : "r"(ADDR))

// ================= preprocessing =================
__global__ __launch_bounds__(256)
void transpose_f16(const float* __restrict__ W, __half* __restrict__ T, int K, int N)
{
    __shared__ float t[32][33];
    const int tx = threadIdx.x & 31, ty = threadIdx.x >> 5;
    const int kb = blockIdx.y * 32, nb = blockIdx.x * 32;
    #pragma unroll
    for (int i = 0; i < 4; i++)
        t[ty + i * 8][tx] = W[(size_t)(kb + ty + i * 8) * N + nb + tx];
    __syncthreads();
    #pragma unroll
    for (int i = 0; i < 4; i++)
        T[(size_t)(nb + ty + i * 8) * K + kb + tx] = __float2half(t[tx][ty + i * 8]);
}

__global__ __launch_bounds__(256)
void convert_f16(const float* __restrict__ X, __half* __restrict__ H, int n)
{
    int i = (blockIdx.x * 256 + threadIdx.x) * 8;
    if (i < n) {
        float4 a = *(const float4*)&X[i];
        float4 b = *(const float4*)&X[i + 4];
        __half2 h0 = __floats2half2_rn(a.x, a.y);
        __half2 h1 = __floats2half2_rn(a.z, a.w);
        __half2 h2 = __floats2half2_rn(b.x, b.y);
        __half2 h3 = __floats2half2_rn(b.z, b.w);
        *(uint4*)&H[i] = make_uint4(*(uint32_t*)&h0, *(uint32_t*)&h1,
                                    *(uint32_t*)&h2, *(uint32_t*)&h3);
    }
}

// ================= fp16 GEMM (R15 verbatim, proven) =================
#define GW 36
#define GTILE (128 * GW)
#define GEMM_SMEM_BYTES (4 * GTILE * 4)    // 73728 B

__global__ __launch_bounds__(256)
void gemm_f16s(const __half* __restrict__ A, const __half* __restrict__ B,
               float* __restrict__ C, int M, int N, int K)
{
    extern __shared__ uint32_t sg[];
    const uint32_t sbase = smem_u32(sg);
    const int tid  = threadIdx.x;
    const int lane = tid & 31;
    const int warp = tid >> 5;
    const int wm   = (warp >> 2) * 64;
    const int wn   = (warp & 3) * 32;
    const int m0   = blockIdx.y * 128;
    const int n0   = blockIdx.x * 128;
    const int lq   = lane >> 2, lr = lane & 3;

    const int srow = tid >> 1;
    const int sh   = (tid & 1) * 32;
    const __half* Ap = A + (size_t)(m0 + srow) * K + sh;
    const __half* Bp = B + (size_t)(n0 + srow) * K + sh;
    const uint32_t wst = srow * GW + (tid & 1) * 16;

    const uint32_t a_lane = (((lane & 15) + wm) * GW + (lane >> 4) * 4) * 4;
    const uint32_t b_lane = (((lane & 7) + wn + (lane >> 4) * 8) * GW
                             + ((lane >> 3) & 1) * 4) * 4;

    float c[4][4][4];
    #pragma unroll
    for (int mt = 0; mt < 4; mt++)
        #pragma unroll
        for (int nt = 0; nt < 4; nt++)
            #pragma unroll
            for (int e = 0; e < 4; e++) c[mt][nt][e] = 0.f;

    const int KT = K >> 6;

    #pragma unroll
    for (int i = 0; i < 4; i++) {
        *(uint4*)&sg[0 * GTILE + wst + i * 4] = *(const uint4*)(Ap + i * 8);
        *(uint4*)&sg[1 * GTILE + wst + i * 4] = *(const uint4*)(Bp + i * 8);
    }
    __syncthreads();

    int buf = 0;
    for (int kt = 0; kt < KT; kt++) {
        uint4 ra[4], rb[4];
        const bool has_next = (kt + 1 < KT);
        if (has_next) {
            const __half* ap = Ap + (size_t)(kt + 1) * 64;
            const __half* bp = Bp + (size_t)(kt + 1) * 64;
            #pragma unroll
            for (int i = 0; i < 4; i++) {
                ra[i] = *(const uint4*)(ap + i * 8);
                rb[i] = *(const uint4*)(bp + i * 8);
            }
        }

        const uint32_t abase = sbase + (uint32_t)(buf * 2 * GTILE) * 4;
        const uint32_t bbase = abase + (uint32_t)GTILE * 4;
        #pragma unroll
        for (int ks = 0; ks < 4; ks++) {
            const uint32_t koff = (uint32_t)(ks * 8) * 4;
            uint32_t af[4][4], bf[2][4];
            #pragma unroll
            for (int mt = 0; mt < 4; mt++)
                LDSM_X4(af[mt][0], af[mt][1], af[mt][2], af[mt][3],
                        abase + (uint32_t)(mt * 16 * GW) * 4 + koff + a_lane);
            #pragma unroll
            for (int t = 0; t < 2; t++)
                LDSM_X4(bf[t][0], bf[t][1], bf[t][2], bf[t][3],
                        bbase + (uint32_t)(t * 16 * GW) * 4 + koff + b_lane);
            #pragma unroll
            for (int mt = 0; mt < 4; mt++)
                #pragma unroll
                for (int nt = 0; nt < 4; nt++)
                    MMA_F16(c[mt][nt][0], c[mt][nt][1], c[mt][nt][2], c[mt][nt][3],
                            af[mt][0], af[mt][1], af[mt][2], af[mt][3],
                            bf[nt >> 1][(nt & 1) * 2], bf[nt >> 1][(nt & 1) * 2 + 1]);
        }

        if (has_next) {
            uint32_t* dst = sg + (buf ^ 1) * 2 * GTILE;
            #pragma unroll
            for (int i = 0; i < 4; i++) {
                *(uint4*)&dst[wst + i * 4]         = ra[i];
                *(uint4*)&dst[GTILE + wst + i * 4] = rb[i];
            }
            __syncthreads();
            buf ^= 1;
        }
    }

    #pragma unroll
    for (int mt = 0; mt < 4; mt++) {
        #pragma unroll
        for (int nt = 0; nt < 4; nt++) {
            int r  = m0 + wm + mt * 16 + lq;
            int cc = n0 + wn + nt * 8 + 2 * lr;
            *(float2*)&C[(size_t)r * N + cc]       = make_float2(c[mt][nt][0], c[mt][nt][1]);
            *(float2*)&C[(size_t)(r + 8) * N + cc] = make_float2(c[mt][nt][2], c[mt][nt][3]);
        }
    }
}

// ---------------- RMSNorm + RoPE, fp32 in place (proven) ----------------
__global__ __launch_bounds__(128)
void norm_rope_kernel(float* __restrict__ data,
                      const float* __restrict__ cosb, const float* __restrict__ sinb,
                      const float* __restrict__ scale, int heads, float extra_scale)
{
    const int r = blockIdx.x;
    const int s = (r / heads) % SS;
    const int d = threadIdx.x;
    float* row = data + (size_t)r * HD;

    float val = row[d];
    float sq = val * val;
    #pragma unroll
    for (int off = 16; off; off >>= 1)
        sq += __shfl_xor_sync(0xffffffffu, sq, off);

    __shared__ float red[4];
    if ((d & 31) == 0) red[d >> 5] = sq;
    __syncthreads();
    float ss = red[0] + red[1] + red[2] + red[3];
    float rinv = rsqrtf(ss * (1.0f / HD) + EPS);
    float nrm = val * rinv * scale[d];

    __shared__ float buf[HD];
    buf[d] = nrm;
    __syncthreads();
    float partner = (d < HD / 2) ? -buf[d + HD / 2] : buf[d - HD / 2];
    float out = nrm * cosb[(size_t)s * HD + d] + partner * sinb[(size_t)s * HD + d];
    row[d] = out * extra_scale;
}

// ================= causal flash attention (fragment loads -> ldmatrix) =========
// Layouts identical to R14/R15 (proven). Only the four fragment-load sites
// switch to ldmatrix.x4, with lane maps transcribed from the proven GEMM:
//   A-map: row = base + (lane&15), k-word-off = (lane>>4)*4
//   B-map: row = t*16 + (lane&7) + (lane>>4)*8, k-word-off = ((lane>>3)&1)*4
// Strides 68 and 36 are both ≡ 4 (mod 32) -> 8 distinct banks per phase.
#define QH_STR 68
#define VT_STR 36
#define PS_STR 36
#define QS_OFF 0
#define KS_OFF (64 * QH_STR)            // 4352
#define VT_OFF (KS_OFF + 64 * QH_STR)   // 8704
#define PS_OFF (VT_OFF + 128 * VT_STR)  // 13312
#define ATT_SMEM_U32 (PS_OFF + 64 * PS_STR)    // 15616
#define ATT_SMEM_BYTES (ATT_SMEM_U32 * 4)      // 62464

__global__ __launch_bounds__(128)
void attn_hyb(const float* __restrict__ q, const float* __restrict__ k,
              const float* __restrict__ v, __half* __restrict__ ctx)
{
    extern __shared__ uint32_t sm[];
    uint32_t* Qs = sm + QS_OFF;
    uint32_t* Ks = sm + KS_OFF;
    uint32_t* Vt = sm + VT_OFF;
    uint32_t* Ps = sm + PS_OFF;
    const uint32_t sbase  = smem_u32(sm);
    const uint32_t qbase  = sbase + QS_OFF * 4;
    const uint32_t kbase  = sbase + KS_OFF * 4;
    const uint32_t vtbase = sbase + VT_OFF * 4;
    const uint32_t psbase = sbase + PS_OFF * 4;

    const int qb = blockIdx.x, h = blockIdx.y, b = blockIdx.z;
    const int kvh = h / GRP;
    const int q0 = qb * 64;
    const int tid = threadIdx.x;
    const int lane = tid & 31;
    const int warp = tid >> 5;       // 0..3
    const int wm = warp * 16;
    const int lq = lane >> 2;
    const int lr = lane & 3;

    // ldmatrix per-lane byte offsets (maps proven in gemm_f16s)
    const uint32_t aq_lane = (((lane & 15) + wm) * QH_STR + (lane >> 4) * 4) * 4;
    const uint32_t bk_lane = (((lane & 7) + (lane >> 4) * 8) * QH_STR
                              + ((lane >> 3) & 1) * 4) * 4;
    const uint32_t ap_lane = (((lane & 15) + wm) * PS_STR + (lane >> 4) * 4) * 4;
    const uint32_t bv_lane = (((lane & 7) + (lane >> 4) * 8) * VT_STR
                              + ((lane >> 3) & 1) * 4) * 4;

    // Q tile staging (proven)
    for (int idx = tid; idx < 64 * 32; idx += 128) {
        int i  = idx >> 5;
        int c4 = idx & 31;
        float4 vq = *(const float4*)&q[((((size_t)b * SS + q0 + i) * NH) + h) * HD + c4 * 4];
        __half2 h0 = __floats2half2_rn(vq.x, vq.y);
        __half2 h1 = __floats2half2_rn(vq.z, vq.w);
        *(uint2*)&Qs[i * QH_STR + c4 * 2] = make_uint2(*(uint32_t*)&h0, *(uint32_t*)&h1);
    }

    float o[16][4];
    #pragma unroll
    for (int nt = 0; nt < 16; nt++)
        #pragma unroll
        for (int e = 0; e < 4; e++) o[nt][e] = 0.f;
    float mrow[2] = {-1e30f, -1e30f};
    float lrow[2] = {0.f, 0.f};

    for (int kb = 0; kb <= qb; kb++) {
        const int k0 = kb * 64;
        __syncthreads();

        for (int idx = tid; idx < 64 * 32; idx += 128) {
            int j  = idx >> 5;
            int c4 = idx & 31;
            float4 vk = *(const float4*)&k[(((size_t)b * SS + k0 + j) * NKV + kvh) * HD + c4 * 4];
            __half2 h0 = __floats2half2_rn(vk.x, vk.y);
            __half2 h1 = __floats2half2_rn(vk.z, vk.w);
            *(uint2*)&Ks[j * QH_STR + c4 * 2] = make_uint2(*(uint32_t*)&h0, *(uint32_t*)&h1);
        }
        for (int idx = tid; idx < 128 * 32; idx += 128) {
            int d  = idx & 127;
            int jw = idx >> 7;
            size_t r0 = (((size_t)b * SS + k0 + 2 * jw)     * NKV + kvh) * HD + d;
            size_t r1 = (((size_t)b * SS + k0 + 2 * jw + 1) * NKV + kvh) * HD + d;
            __half2 hv = __floats2half2_rn(v[r0], v[r1]);
            Vt[d * VT_STR + jw] = *(uint32_t*)&hv;
        }
        __syncthreads();

        const bool active = (k0 <= q0 + wm + 15);
        if (active) {
            // ---- S = Q K^T (fp16, ldmatrix) ----
            float s[8][4];
            #pragma unroll
            for (int nt = 0; nt < 8; nt++)
                #pragma unroll
                for (int e = 0; e < 4; e++) s[nt][e] = 0.f;

            #pragma unroll
            for (int ks = 0; ks < 8; ks++) {
                const uint32_t koff = (uint32_t)(ks * 8) * 4;
                uint32_t af[4], bf[4][4];
                LDSM_X4(af[0], af[1], af[2], af[3], qbase + koff + aq_lane);
                #pragma unroll
                for (int t = 0; t < 4; t++)
                    LDSM_X4(bf[t][0], bf[t][1], bf[t][2], bf[t][3],
                            kbase + (uint32_t)(t * 16 * QH_STR) * 4 + koff + bk_lane);
                #pragma unroll
                for (int nt = 0; nt < 8; nt++)
                    MMA_F16(s[nt][0], s[nt][1], s[nt][2], s[nt][3],
                            af[0], af[1], af[2], af[3],
                            bf[nt >> 1][(nt & 1) * 2], bf[nt >> 1][(nt & 1) * 2 + 1]);
            }

            // causal mask on the diagonal tile
            if (kb == qb) {
                int i0 = q0 + wm + lq;
                #pragma unroll
                for (int nt = 0; nt < 8; nt++) {
                    int j0 = k0 + nt * 8 + 2 * lr;
                    if (j0     > i0)     s[nt][0] = -1e30f;
                    if (j0 + 1 > i0)     s[nt][1] = -1e30f;
                    if (j0     > i0 + 8) s[nt][2] = -1e30f;
                    if (j0 + 1 > i0 + 8) s[nt][3] = -1e30f;
                }
            }

            // ---- online softmax (proven) ----
            #pragma unroll
            for (int hh = 0; hh < 2; hh++) {
                float rmax = -1e30f;
                #pragma unroll
                for (int nt = 0; nt < 8; nt++)
                    rmax = fmaxf(rmax, fmaxf(s[nt][2 * hh], s[nt][2 * hh + 1]));
                rmax = fmaxf(rmax, __shfl_xor_sync(0xffffffffu, rmax, 1));
                rmax = fmaxf(rmax, __shfl_xor_sync(0xffffffffu, rmax, 2));

                float mnew  = fmaxf(mrow[hh], rmax);
                float alpha = __expf(mrow[hh] - mnew);
                mrow[hh] = mnew;

                float rsum = 0.f;
                int prow = (wm + lq + 8 * hh) * PS_STR;
                #pragma unroll
                for (int nt = 0; nt < 8; nt++) {
                    float p0 = __expf(s[nt][2 * hh]     - mnew);
                    float p1 = __expf(s[nt][2 * hh + 1] - mnew);
                    rsum += p0 + p1;
                    __half2 hp = __floats2half2_rn(p0, p1);
                    Ps[prow + nt * 4 + lr] = *(uint32_t*)&hp;
                }
                rsum += __shfl_xor_sync(0xffffffffu, rsum, 1);
                rsum += __shfl_xor_sync(0xffffffffu, rsum, 2);
                lrow[hh] = lrow[hh] * alpha + rsum;

                #pragma unroll
                for (int nt = 0; nt < 16; nt++) {
                    o[nt][2 * hh]     *= alpha;
                    o[nt][2 * hh + 1] *= alpha;
                }
            }
            __syncwarp();

            // ---- O += P V (fp16, ldmatrix) ----
            #pragma unroll
            for (int ks = 0; ks < 4; ks++) {
                const uint32_t koff = (uint32_t)(ks * 8) * 4;
                uint32_t af[4], bf[8][4];
                LDSM_X4(af[0], af[1], af[2], af[3], psbase + koff + ap_lane);
                #pragma unroll
                for (int t = 0; t < 8; t++)
                    LDSM_X4(bf[t][0], bf[t][1], bf[t][2], bf[t][3],
                            vtbase + (uint32_t)(t * 16 * VT_STR) * 4 + koff + bv_lane);
                #pragma unroll
                for (int nt = 0; nt < 16; nt++)
                    MMA_F16(o[nt][0], o[nt][1], o[nt][2], o[nt][3],
                            af[0], af[1], af[2], af[3],
                            bf[nt >> 1][(nt & 1) * 2], bf[nt >> 1][(nt & 1) * 2 + 1]);
            }
        }
    }

    // epilogue: divide by l, write ctx fp16 (b,s,h,d)
    #pragma unroll
    for (int hh = 0; hh < 2; hh++) {
        float inv = 1.0f / lrow[hh];
        int row = q0 + wm + lq + 8 * hh;
        size_t base = (((size_t)b * SS + row) * NH + h) * HD;
        #pragma unroll
        for (int nt = 0; nt < 16; nt++) {
            int d = nt * 8 + 2 * lr;
            __half2 vv = __floats2half2_rn(o[nt][2 * hh] * inv, o[nt][2 * hh + 1] * inv);
            *(__half2*)&ctx[base + d] = vv;
        }
    }
}

// ---------------- launch ----------------
extern "C" void kernel_launch(void* const* d_in, const int* in_sizes, int n_in,
                              void* d_out, int out_size)
{
    const float* x       = (const float*)d_in[0];
    const float* cosb    = (const float*)d_in[2];
    const float* sinb    = (const float*)d_in[3];
    const float* Wq      = (const float*)d_in[4];
    const float* Wk      = (const float*)d_in[5];
    const float* Wv      = (const float*)d_in[6];
    const float* Wo      = (const float*)d_in[7];
    const float* q_scale = (const float*)d_in[8];
    const float* k_scale = (const float*)d_in[9];
    float* out = (float*)d_out;

    float *q, *k, *v;
    cudaGetSymbolAddress((void**)&q, g_q);
    cudaGetSymbolAddress((void**)&k, g_k);
    cudaGetSymbolAddress((void**)&v, g_v);
    __half *xh, *ch, *wqT, *wkT, *wvT, *woT;
    cudaGetSymbolAddress((void**)&xh,  g_xh);
    cudaGetSymbolAddress((void**)&ch,  g_ch);
    cudaGetSymbolAddress((void**)&wqT, g_wqT);
    cudaGetSymbolAddress((void**)&wkT, g_wkT);
    cudaGetSymbolAddress((void**)&wvT, g_wvT);
    cudaGetSymbolAddress((void**)&woT, g_woT);

    const int M = BB * SS;   // 4096

    // preprocessing
    transpose_f16<<<dim3((NH * HD) / 32, DIN / 32), 256>>>(Wq, wqT, DIN, NH * HD);
    transpose_f16<<<dim3((NKV * HD) / 32, DIN / 32), 256>>>(Wk, wkT, DIN, NKV * HD);
    transpose_f16<<<dim3((NKV * HD) / 32, DIN / 32), 256>>>(Wv, wvT, DIN, NKV * HD);
    transpose_f16<<<dim3(DIN / 32, (NH * HD) / 32), 256>>>(Wo, woT, NH * HD, DIN);
    convert_f16<<<M * DIN / 8 / 256, 256>>>(x, xh, M * DIN);

    // projections (fp16 mma + ldmatrix, fp32 out)
    cudaFuncSetAttribute(gemm_f16s, cudaFuncAttributeMaxDynamicSharedMemorySize,
                         GEMM_SMEM_BYTES);
    gemm_f16s<<<dim3((NH * HD) / 128, M / 128), 256, GEMM_SMEM_BYTES>>>(
        xh, wqT, q, M, NH * HD, DIN);
    gemm_f16s<<<dim3((NKV * HD) / 128, M / 128), 256, GEMM_SMEM_BYTES>>>(
        xh, wkT, k, M, NKV * HD, DIN);
    gemm_f16s<<<dim3((NKV * HD) / 128, M / 128), 256, GEMM_SMEM_BYTES>>>(
        xh, wvT, v, M, NKV * HD, DIN);

    // rmsnorm + rope (fp32)
    norm_rope_kernel<<<BB * SS * NH,  128>>>(q, cosb, sinb, q_scale, NH,  SCALING);
    norm_rope_kernel<<<BB * SS * NKV, 128>>>(k, cosb, sinb, k_scale, NKV, 1.0f);

    // attention (all-fp16 MMA + ldmatrix, 64 q/CTA, 3 CTAs/SM), writes fp16 ctx
    cudaFuncSetAttribute(attn_hyb, cudaFuncAttributeMaxDynamicSharedMemorySize,
                         ATT_SMEM_BYTES);
    attn_hyb<<<dim3(SS / 64, NH, BB), 128, ATT_SMEM_BYTES>>>(q, k, v, ch);

    // output projection (fp16 ctx -> fp32 out)
    gemm_f16s<<<dim3(DIN / 128, M / 128), 256, GEMM_SMEM_BYTES>>>(
        ch, woT, out, M, DIN, DIN);
}